// round 8
// baseline (speedup 1.0000x reference)
#include <cuda_runtime.h>
#include <cuda_fp16.h>
#include <cstdint>

// B=4, N=4096, D=256
// scores = (V V^T)/16 ; edges = softsign(scores)
// dstate = edges @ state ; dval = edges @ val
// fp16 split pipeline (phase A 3-term hi/lo, phase B 2-term), 512 threads:
// warp (mw, nh) owns 16 M-rows x one j/col half. E round-trips via smem.

#define BATCH 4
#define NN 4096
#define DD 256
#define BM 128
#define BJH 32
#define NHALF (NN / BJH)
#define THREADS 512
#define ROWB 528      // fp16 tile row pitch: bank-step 4, conflict-free ldsm
#define EPITCH 80     // E row pitch: bank-step 20, conflict-free ldsm

static constexpr uint32_t S_VIH = 0;                     // 128*528 = 67584
static constexpr uint32_t S_VIL = 67584;
static constexpr uint32_t S_VJ0 = 135168;                // 32 hi + 32 lo rows
static constexpr uint32_t VJ_LO = 16896;                 // 32*528
static constexpr uint32_t VJBUF = 33792;
static constexpr uint32_t S_VJ1 = S_VJ0 + VJBUF;         // 168960
static constexpr uint32_t S_E   = S_VJ1 + VJBUF;         // 202752: 128*80 = 10240
static constexpr uint32_t S_ST0 = 212992;                // 128 B
static constexpr uint32_t S_ST1 = 213120;
static constexpr uint32_t S_RED = 213248;                // 128*2*4 = 1024
static constexpr uint32_t SMEM_BYTES = 214272;

__device__ __half g_vhi[(size_t)BATCH * NN * DD];
__device__ __half g_vlo[(size_t)BATCH * NN * DD];

__device__ __forceinline__ uint32_t smem_u32(const void* p) {
    uint32_t a;
    asm("{ .reg .u64 t; cvta.to.shared.u64 t, %1; cvt.u32.u64 %0, t; }" : "=r"(a) : "l"(p));
    return a;
}
__device__ __forceinline__ void cpa16(uint32_t dst, const void* src) {
    asm volatile("cp.async.cg.shared.global [%0], [%1], 16;" :: "r"(dst), "l"(src) : "memory");
}
#define CP_COMMIT() asm volatile("cp.async.commit_group;" ::: "memory")
#define CP_WAIT1()  asm volatile("cp.async.wait_group 1;" ::: "memory")

__device__ __forceinline__ void ldm_x4(uint32_t* r, uint32_t addr) {
    asm volatile("ldmatrix.sync.aligned.m8n8.x4.shared.b16 {%0,%1,%2,%3}, [%4];"
        : "=r"(r[0]), "=r"(r[1]), "=r"(r[2]), "=r"(r[3]) : "r"(addr));
}
__device__ __forceinline__ void ldm_x4_t(uint32_t* r, uint32_t addr) {
    asm volatile("ldmatrix.sync.aligned.m8n8.x4.trans.shared.b16 {%0,%1,%2,%3}, [%4];"
        : "=r"(r[0]), "=r"(r[1]), "=r"(r[2]), "=r"(r[3]) : "r"(addr));
}
__device__ __forceinline__ void mma16816(float* c, const uint32_t* a, const uint32_t* b) {
    asm volatile("mma.sync.aligned.m16n8k16.row.col.f32.f16.f16.f32 "
        "{%0,%1,%2,%3}, {%4,%5,%6,%7}, {%8,%9}, {%0,%1,%2,%3};"
        : "+f"(c[0]), "+f"(c[1]), "+f"(c[2]), "+f"(c[3])
        : "r"(a[0]), "r"(a[1]), "r"(a[2]), "r"(a[3]), "r"(b[0]), "r"(b[1]));
}
__device__ __forceinline__ uint32_t h2pk(float x, float y) {
    __half2 t = __floats2half2_rn(x, y);
    return *reinterpret_cast<uint32_t*>(&t);
}
__device__ __forceinline__ uint32_t h2lo(float x, float y) {
    float hx = __half2float(__float2half_rn(x));
    float hy = __half2float(__float2half_rn(y));
    __half2 t = __floats2half2_rn(x - hx, y - hy);
    return *reinterpret_cast<uint32_t*>(&t);
}

__global__ __launch_bounds__(256) void split_kernel(const float* __restrict__ val) {
    const int b = blockIdx.y, n0 = blockIdx.x * 64;
    const size_t base = ((size_t)b * NN + n0) * DD;
    #pragma unroll
    for (int k = 0; k < 16; k++) {
        int u = threadIdx.x + 256 * k;
        float4 v = *(const float4*)(val + base + (size_t)u * 4);
        *(uint2*)(g_vhi + base + (size_t)u * 4) = make_uint2(h2pk(v.x, v.y), h2pk(v.z, v.w));
        *(uint2*)(g_vlo + base + (size_t)u * 4) = make_uint2(h2lo(v.x, v.y), h2lo(v.z, v.w));
    }
}

__global__ __launch_bounds__(THREADS, 1)
void prop_hmma(const float* __restrict__ state,
               float* __restrict__ dstate, float* __restrict__ dval)
{
    extern __shared__ char smem[];
    const uint32_t sb = smem_u32(smem);
    const int tid = threadIdx.x, l = tid & 31, wid = tid >> 5;
    const int mw = wid >> 1, nh = wid & 1;       // M-warp (0-7), col-half (0-1)
    const int b = blockIdx.y, i0 = blockIdx.x * BM;
    const size_t vbase = (size_t)b * NN * DD;

    // ---- prologue fill: Vi (hi/lo) + j-half 0 ----
    {
        #pragma unroll
        for (int k = 0; k < 16; k++) {           // Vi: 8192 chunks
            int u = tid + 512 * k;
            int half = u >> 12, rem = u & 4095;
            int row = rem >> 5, ch = rem & 31;
            cpa16(sb + (half ? S_VIL : S_VIH) + (uint32_t)(row * ROWB + ch * 16),
                  (half ? g_vlo : g_vhi) + vbase + (size_t)(i0 + row) * DD + ch * 8);
        }
        #pragma unroll
        for (int k = 0; k < 4; k++) {            // Vj half 0: 2048 chunks
            int u = tid + 512 * k;
            int half = u >> 10, rem = u & 1023;
            int row = rem >> 5, ch = rem & 31;
            cpa16(sb + S_VJ0 + (half ? VJ_LO : 0u) + (uint32_t)(row * ROWB + ch * 16),
                  (half ? g_vlo : g_vhi) + vbase + (size_t)row * DD + ch * 8);
        }
        if (tid < 8) cpa16(sb + S_ST0 + tid * 16, state + (size_t)b * NN + tid * 4);
        CP_COMMIT();
    }

    // per-thread ldmatrix offsets
    const uint32_t offA  = (uint32_t)((l & 15) * ROWB + (l >> 4) * 16);
    const uint32_t offAE = (uint32_t)((l & 15) * EPITCH + (l >> 4) * 16);
    const uint32_t offBn = (uint32_t)(((l & 7) + ((l & 16) ? 8 : 0)) * ROWB + ((l >> 3) & 1) * 16);
    const uint32_t viH = sb + S_VIH + mw * (16 * ROWB) + offA;
    const uint32_t viL = sb + S_VIL + mw * (16 * ROWB) + offA;
    const uint32_t eA  = sb + S_E + mw * (16 * EPITCH) + offAE;

    float dacc[16][4];
    #pragma unroll
    for (int t = 0; t < 16; t++) { dacc[t][0] = dacc[t][1] = dacc[t][2] = dacc[t][3] = 0.f; }
    float ds0 = 0.f, ds1 = 0.f;
    const float scale = 0.0625f;
    const int c0 = 2 * (l & 3);

    for (int h = 0; h < NHALF; h++) {
        // ---- issue fill(h+1) ----
        {
            int hn = h + 1;
            if (hn < NHALF) {
                const int j0 = hn * BJH;
                uint32_t bufb = sb + ((hn & 1) ? S_VJ1 : S_VJ0);
                #pragma unroll
                for (int k = 0; k < 4; k++) {
                    int u = tid + 512 * k;
                    int half = u >> 10, rem = u & 1023;
                    int row = rem >> 5, ch = rem & 31;
                    cpa16(bufb + (half ? VJ_LO : 0u) + (uint32_t)(row * ROWB + ch * 16),
                          (half ? g_vlo : g_vhi) + vbase + (size_t)(j0 + row) * DD + ch * 8);
                }
                if (tid < 8)
                    cpa16(sb + ((hn & 1) ? S_ST1 : S_ST0) + tid * 16,
                          state + (size_t)b * NN + j0 + tid * 4);
            }
            CP_COMMIT();
        }
        CP_WAIT1();
        __syncthreads();

        const uint32_t bufb = sb + ((h & 1) ? S_VJ1 : S_VJ0);
        const uint32_t vjBn = bufb + nh * (16 * ROWB) + offBn;   // phase A B, this col-half
        const uint32_t vjT  = bufb + offA;                       // phase B B (trans)
        const float* stp = (const float*)(smem + ((h & 1) ? S_ST1 : S_ST0));

        // ---- Phase A: S[16 x 16] per warp, 3-term, term-major ----
        float sacc[2][4];
        sacc[0][0] = sacc[0][1] = sacc[0][2] = sacc[0][3] = 0.f;
        sacc[1][0] = sacc[1][1] = sacc[1][2] = sacc[1][3] = 0.f;

        #pragma unroll
        for (int s = 0; s < 16; s++) {
            uint32_t ah[4], al[4], bh[4], bl[4];
            ldm_x4(ah, viH + s * 32);
            ldm_x4(al, viL + s * 32);
            ldm_x4(bh, vjBn + s * 32);
            ldm_x4(bl, vjBn + VJ_LO + s * 32);
            mma16816(sacc[0], ah, bh + 0);
            mma16816(sacc[1], ah, bh + 2);
            mma16816(sacc[0], ah, bl + 0);
            mma16816(sacc[1], ah, bl + 2);
            mma16816(sacc[0], al, bh + 0);
            mma16816(sacc[1], al, bh + 2);
        }

        // ---- epilogue: softsign, dstate partial, E -> smem (fp16) ----
        #pragma unroll
        for (int t = 0; t < 2; t++) {
            float f0 = sacc[t][0] * scale, f1 = sacc[t][1] * scale;
            float f2 = sacc[t][2] * scale, f3 = sacc[t][3] * scale;
            float e0 = __fdividef(f0, 1.0f + fabsf(f0));
            float e1 = __fdividef(f1, 1.0f + fabsf(f1));
            float e2 = __fdividef(f2, 1.0f + fabsf(f2));
            float e3 = __fdividef(f3, 1.0f + fabsf(f3));
            int col = nh * 16 + t * 8 + c0;
            float sA = stp[col], sB = stp[col + 1];
            ds0 += e0 * sA + e1 * sB;
            ds1 += e2 * sA + e3 * sB;
            uint32_t ea = sb + S_E + (uint32_t)((mw * 16 + (l >> 2)) * EPITCH + col * 2);
            asm volatile("st.shared.b32 [%0], %1;" :: "r"(ea), "r"(h2pk(e0, e1)));
            asm volatile("st.shared.b32 [%0], %1;" :: "r"(ea + 8 * EPITCH), "r"(h2pk(e2, e3)));
        }
        __syncthreads();   // E visible to both warps of the pair

        // ---- Phase B: dval[16 x 128] += E[16x32] @ Vj[32 x this col-half], 2-term ----
        #pragma unroll
        for (int kt = 0; kt < 2; kt++) {
            uint32_t aE[4];
            ldm_x4(aE, eA + kt * 32);
            uint32_t tb = vjT + kt * (16 * ROWB) + nh * 256;
            #pragma unroll
            for (int blk = 0; blk < 2; blk++) {
                uint32_t bh[4][4], bl[4][4];
                #pragma unroll
                for (int j = 0; j < 4; j++) {
                    int nt2 = blk * 4 + j;
                    ldm_x4_t(bh[j], tb + nt2 * 32);
                    ldm_x4_t(bl[j], tb + VJ_LO * 1u + nt2 * 32);
                }
                #pragma unroll
                for (int j = 0; j < 4; j++) {            // E * Vhi
                    int nt2 = blk * 4 + j;
                    mma16816(dacc[2 * nt2],     aE, bh[j] + 0);
                    mma16816(dacc[2 * nt2 + 1], aE, bh[j] + 2);
                }
                #pragma unroll
                for (int j = 0; j < 4; j++) {            // E * Vlo
                    int nt2 = blk * 4 + j;
                    mma16816(dacc[2 * nt2],     aE, bl[j] + 0);
                    mma16816(dacc[2 * nt2 + 1], aE, bl[j] + 2);
                }
            }
        }
        __syncthreads();   // E + Vj buffer reads done before next-iter overwrite
    }

    // ---- write dval (warp owns rows mw*16..+16, cols nh*128..+128) ----
    {
        const int row = i0 + mw * 16 + (l >> 2);
        float* d0 = dval + (size_t)b * NN * DD + (size_t)row * DD + nh * 128;
        float* d1 = d0 + 8 * DD;
        #pragma unroll
        for (int nt = 0; nt < 16; nt++) {
            int c = 8 * nt + c0;
            *(float2*)(d0 + c) = make_float2(dacc[nt][0], dacc[nt][1]);
            *(float2*)(d1 + c) = make_float2(dacc[nt][2], dacc[nt][3]);
        }
    }
    // ---- dstate: lane-reduce, then cross-half reduce via smem ----
    ds0 += __shfl_xor_sync(0xFFFFFFFFu, ds0, 1);
    ds0 += __shfl_xor_sync(0xFFFFFFFFu, ds0, 2);
    ds1 += __shfl_xor_sync(0xFFFFFFFFu, ds1, 1);
    ds1 += __shfl_xor_sync(0xFFFFFFFFu, ds1, 2);
    float* red = (float*)(smem + S_RED);
    if ((l & 3) == 0) {
        int r = mw * 16 + (l >> 2);
        red[r * 2 + nh]       = ds0;
        red[(r + 8) * 2 + nh] = ds1;
    }
    __syncthreads();
    if (tid < 128)
        dstate[(size_t)b * NN + i0 + tid] = red[tid * 2] + red[tid * 2 + 1];
}

extern "C" void kernel_launch(void* const* d_in, const int* in_sizes, int n_in,
                              void* d_out, int out_size)
{
    const float* val   = (const float*)d_in[0];   // [B, N, D]
    const float* state = (const float*)d_in[1];   // [B, N]
    float* dstate = (float*)d_out;                // [B, N]
    float* dval   = dstate + (size_t)BATCH * NN;  // [B, N, D]
    (void)in_sizes; (void)n_in; (void)out_size;

    dim3 gs(NN / 64, BATCH);
    split_kernel<<<gs, 256>>>(val);

    cudaFuncSetAttribute(prop_hmma,
                         cudaFuncAttributeMaxDynamicSharedMemorySize, (int)SMEM_BYTES);
    dim3 grid(NN / BM, BATCH);
    prop_hmma<<<grid, THREADS, SMEM_BYTES>>>(state, dstate, dval);
}

// round 9
// speedup vs baseline: 1.4512x; 1.4512x over previous
#include <cuda_runtime.h>
#include <cuda_fp16.h>
#include <cstdint>

// B=4, N=4096, D=256
// scores = (V V^T)/16 ; edges = softsign(scores)
// dstate = edges @ state ; dval = edges @ val
// fp16 split pipeline: phase A 3-term (hi/lo), phase B 1-term (E fp16 x V_hi).
// cp.async double-buffered, term-major mma scheduling. (R6 minus phase-B lo.)

#define BATCH 4
#define NN 4096
#define DD 256
#define BM 128
#define BJH 32            // half j-tile (pipeline stage)
#define NHALF (NN / BJH)  // 128
#define THREADS 256
#define ROWB 528          // 33 x 16B per 256-elem fp16 row (conflict-free padding)

static constexpr uint32_t S_VIH = 0;
static constexpr uint32_t S_VIL = 128u * ROWB;
static constexpr uint32_t S_VJ0 = 2u * 128u * ROWB;
static constexpr uint32_t S_VJ1 = S_VJ0 + 64u * ROWB;
static constexpr uint32_t VJ_LO = 32u * ROWB;
static constexpr uint32_t S_ST0 = S_VJ1 + 64u * ROWB;
static constexpr uint32_t S_ST1 = S_ST0 + 128u;
static constexpr uint32_t SMEM_BYTES = S_ST1 + 128u;

__device__ __half g_vhi[(size_t)BATCH * NN * DD];
__device__ __half g_vlo[(size_t)BATCH * NN * DD];

__device__ __forceinline__ uint32_t smem_u32(const void* p) {
    uint32_t a;
    asm("{ .reg .u64 t; cvta.to.shared.u64 t, %1; cvt.u32.u64 %0, t; }" : "=r"(a) : "l"(p));
    return a;
}
__device__ __forceinline__ void cpa16(uint32_t dst, const void* src) {
    asm volatile("cp.async.cg.shared.global [%0], [%1], 16;" :: "r"(dst), "l"(src) : "memory");
}
#define CP_COMMIT() asm volatile("cp.async.commit_group;" ::: "memory")
#define CP_WAIT1()  asm volatile("cp.async.wait_group 1;" ::: "memory")

__device__ __forceinline__ void ldm_x4(uint32_t* r, uint32_t addr) {
    asm volatile("ldmatrix.sync.aligned.m8n8.x4.shared.b16 {%0,%1,%2,%3}, [%4];"
        : "=r"(r[0]), "=r"(r[1]), "=r"(r[2]), "=r"(r[3]) : "r"(addr));
}
__device__ __forceinline__ void ldm_x4_t(uint32_t* r, uint32_t addr) {
    asm volatile("ldmatrix.sync.aligned.m8n8.x4.trans.shared.b16 {%0,%1,%2,%3}, [%4];"
        : "=r"(r[0]), "=r"(r[1]), "=r"(r[2]), "=r"(r[3]) : "r"(addr));
}
__device__ __forceinline__ void mma16816(float* c, const uint32_t* a, const uint32_t* b) {
    asm volatile("mma.sync.aligned.m16n8k16.row.col.f32.f16.f16.f32 "
        "{%0,%1,%2,%3}, {%4,%5,%6,%7}, {%8,%9}, {%0,%1,%2,%3};"
        : "+f"(c[0]), "+f"(c[1]), "+f"(c[2]), "+f"(c[3])
        : "r"(a[0]), "r"(a[1]), "r"(a[2]), "r"(a[3]), "r"(b[0]), "r"(b[1]));
}
__device__ __forceinline__ uint32_t h2pk(float x, float y) {
    __half2 t = __floats2half2_rn(x, y);
    return *reinterpret_cast<uint32_t*>(&t);
}
__device__ __forceinline__ uint32_t h2lo(float x, float y) {
    float hx = __half2float(__float2half_rn(x));
    float hy = __half2float(__float2half_rn(y));
    __half2 t = __floats2half2_rn(x - hx, y - hy);
    return *reinterpret_cast<uint32_t*>(&t);
}

__global__ __launch_bounds__(256) void split_kernel(const float* __restrict__ val) {
    const int b = blockIdx.y, n0 = blockIdx.x * 64;
    const size_t base = ((size_t)b * NN + n0) * DD;
    #pragma unroll
    for (int k = 0; k < 16; k++) {
        int u = threadIdx.x + 256 * k;
        float4 v = *(const float4*)(val + base + (size_t)u * 4);
        *(uint2*)(g_vhi + base + (size_t)u * 4) = make_uint2(h2pk(v.x, v.y), h2pk(v.z, v.w));
        *(uint2*)(g_vlo + base + (size_t)u * 4) = make_uint2(h2lo(v.x, v.y), h2lo(v.z, v.w));
    }
}

__global__ __launch_bounds__(THREADS, 1)
void prop_hmma(const float* __restrict__ state,
               float* __restrict__ dstate, float* __restrict__ dval)
{
    extern __shared__ char smem[];
    const uint32_t sb = smem_u32(smem);
    const int tid = threadIdx.x, l = tid & 31, wid = tid >> 5;
    const int b = blockIdx.y, i0 = blockIdx.x * BM;
    const int mrow = wid * 16;
    const size_t vbase = (size_t)b * NN * DD;

    // ---- prologue fill: Vi + j-half 0 ----
    {
        #pragma unroll
        for (int k = 0; k < 32; k++) {
            int u = tid + 256 * k;
            int row = u >> 6, rem = u & 63;
            int half = rem >> 5, ch = rem & 31;
            uint32_t dst = sb + (half ? S_VIL : S_VIH) + (uint32_t)(row * ROWB + ch * 16);
            const __half* src = (half ? g_vlo : g_vhi) + vbase + (size_t)(i0 + row) * DD + ch * 8;
            cpa16(dst, src);
        }
        #pragma unroll
        for (int k = 0; k < 8; k++) {
            int u = tid + 256 * k;
            int row = u >> 6, rem = u & 63;
            int half = rem >> 5, ch = rem & 31;
            uint32_t dst = sb + S_VJ0 + (half ? VJ_LO : 0u) + (uint32_t)(row * ROWB + ch * 16);
            const __half* src = (half ? g_vlo : g_vhi) + vbase + (size_t)row * DD + ch * 8;
            cpa16(dst, src);
        }
        if (tid < 8) cpa16(sb + S_ST0 + tid * 16, state + (size_t)b * NN + tid * 4);
        CP_COMMIT();
    }

    const uint32_t offA  = (uint32_t)((l & 15) * ROWB + (l >> 4) * 16);
    const uint32_t offBn = (uint32_t)(((l & 7) + ((l & 16) ? 8 : 0)) * ROWB + ((l >> 3) & 1) * 16);
    const uint32_t viH = sb + S_VIH + mrow * ROWB + offA;
    const uint32_t viL = sb + S_VIL + mrow * ROWB + offA;

    float dacc[32][4];
    #pragma unroll
    for (int t = 0; t < 32; t++) { dacc[t][0] = dacc[t][1] = dacc[t][2] = dacc[t][3] = 0.f; }
    float ds0 = 0.f, ds1 = 0.f;
    const float scale = 0.0625f;
    const int c0 = 2 * (l & 3);

    for (int h = 0; h < NHALF; h++) {
        // ---- issue fill(h+1) ----
        {
            int hn = h + 1;
            if (hn < NHALF) {
                const int j0 = hn * BJH;
                uint32_t bufb = sb + ((hn & 1) ? S_VJ1 : S_VJ0);
                #pragma unroll
                for (int k = 0; k < 8; k++) {
                    int u = tid + 256 * k;
                    int row = u >> 6, rem = u & 63;
                    int half = rem >> 5, ch = rem & 31;
                    uint32_t dst = bufb + (half ? VJ_LO : 0u) + (uint32_t)(row * ROWB + ch * 16);
                    const __half* src = (half ? g_vlo : g_vhi) + vbase + (size_t)(j0 + row) * DD + ch * 8;
                    cpa16(dst, src);
                }
                if (tid < 8)
                    cpa16(sb + ((hn & 1) ? S_ST1 : S_ST0) + tid * 16,
                          state + (size_t)b * NN + j0 + tid * 4);
            }
            CP_COMMIT();
        }
        CP_WAIT1();
        __syncthreads();

        const uint32_t bufb = sb + ((h & 1) ? S_VJ1 : S_VJ0);
        const uint32_t vjB = bufb + offBn;
        const uint32_t vjT = bufb + offA;
        const float* stp = (const float*)(smem + ((h & 1) ? S_ST1 : S_ST0));

        // ---- Phase A: 3-term fp16, term-major ----
        float sacc[4][4];
        #pragma unroll
        for (int t = 0; t < 4; t++) { sacc[t][0] = sacc[t][1] = sacc[t][2] = sacc[t][3] = 0.f; }

        #pragma unroll
        for (int s = 0; s < 16; s++) {
            uint32_t ah[4], al[4], bh0[4], bh1[4], bl0[4], bl1[4];
            ldm_x4(ah, viH + s * 32);
            ldm_x4(al, viL + s * 32);
            ldm_x4(bh0, vjB + s * 32);
            ldm_x4(bh1, vjB + 16 * ROWB + s * 32);
            ldm_x4(bl0, vjB + VJ_LO + s * 32);
            ldm_x4(bl1, vjB + VJ_LO + 16 * ROWB + s * 32);
            mma16816(sacc[0], ah, bh0 + 0);
            mma16816(sacc[1], ah, bh0 + 2);
            mma16816(sacc[2], ah, bh1 + 0);
            mma16816(sacc[3], ah, bh1 + 2);
            mma16816(sacc[0], ah, bl0 + 0);
            mma16816(sacc[1], ah, bl0 + 2);
            mma16816(sacc[2], ah, bl1 + 0);
            mma16816(sacc[3], ah, bl1 + 2);
            mma16816(sacc[0], al, bh0 + 0);
            mma16816(sacc[1], al, bh0 + 2);
            mma16816(sacc[2], al, bh1 + 0);
            mma16816(sacc[3], al, bh1 + 2);
        }

        // ---- epilogue: softsign (fp32), dstate partial, E -> fp16 a-frags ----
        uint32_t eh[2][4];
        #pragma unroll
        for (int t = 0; t < 4; t++) {
            float f0 = sacc[t][0] * scale, f1 = sacc[t][1] * scale;
            float f2 = sacc[t][2] * scale, f3 = sacc[t][3] * scale;
            float e0 = __fdividef(f0, 1.0f + fabsf(f0));
            float e1 = __fdividef(f1, 1.0f + fabsf(f1));
            float e2 = __fdividef(f2, 1.0f + fabsf(f2));
            float e3 = __fdividef(f3, 1.0f + fabsf(f3));
            float sA = stp[8 * t + c0], sB = stp[8 * t + c0 + 1];
            ds0 += e0 * sA + e1 * sB;
            ds1 += e2 * sA + e3 * sB;
            int kt = t >> 1, hh = (t & 1) * 2;
            eh[kt][hh]     = h2pk(e0, e1);
            eh[kt][hh + 1] = h2pk(e2, e3);
        }

        // ---- Phase B: 1-term (E fp16 x V_hi), blocks of 4, term-major ----
        #pragma unroll
        for (int kt = 0; kt < 2; kt++) {
            uint32_t tb = vjT + kt * (16 * ROWB);
            #pragma unroll
            for (int blk = 0; blk < 4; blk++) {
                uint32_t bh[4][4];
                #pragma unroll
                for (int j = 0; j < 4; j++)
                    ldm_x4_t(bh[j], tb + (blk * 4 + j) * 32);
                #pragma unroll
                for (int j = 0; j < 4; j++) {
                    int nt2 = blk * 4 + j;
                    mma16816(dacc[2 * nt2],     eh[kt], bh[j] + 0);
                    mma16816(dacc[2 * nt2 + 1], eh[kt], bh[j] + 2);
                }
            }
        }
        __syncthreads();
    }

    // ---- write dval ----
    {
        const int row = i0 + mrow + (l >> 2);
        float* d0 = dval + (size_t)b * NN * DD + (size_t)row * DD;
        float* d1 = d0 + 8 * DD;
        #pragma unroll
        for (int nt = 0; nt < 32; nt++) {
            int c = 8 * nt + c0;
            *(float2*)(d0 + c) = make_float2(dacc[nt][0], dacc[nt][1]);
            *(float2*)(d1 + c) = make_float2(dacc[nt][2], dacc[nt][3]);
        }
    }
    // ---- dstate ----
    ds0 += __shfl_xor_sync(0xFFFFFFFFu, ds0, 1);
    ds0 += __shfl_xor_sync(0xFFFFFFFFu, ds0, 2);
    ds1 += __shfl_xor_sync(0xFFFFFFFFu, ds1, 1);
    ds1 += __shfl_xor_sync(0xFFFFFFFFu, ds1, 2);
    if ((l & 3) == 0) {
        int r = i0 + mrow + (l >> 2);
        dstate[(size_t)b * NN + r]     = ds0;
        dstate[(size_t)b * NN + r + 8] = ds1;
    }
}

extern "C" void kernel_launch(void* const* d_in, const int* in_sizes, int n_in,
                              void* d_out, int out_size)
{
    const float* val   = (const float*)d_in[0];   // [B, N, D]
    const float* state = (const float*)d_in[1];   // [B, N]
    float* dstate = (float*)d_out;                // [B, N]
    float* dval   = dstate + (size_t)BATCH * NN;  // [B, N, D]
    (void)in_sizes; (void)n_in; (void)out_size;

    dim3 gs(NN / 64, BATCH);
    split_kernel<<<gs, 256>>>(val);

    cudaFuncSetAttribute(prop_hmma,
                         cudaFuncAttributeMaxDynamicSharedMemorySize, (int)SMEM_BYTES);
    dim3 grid(NN / BM, BATCH);
    prop_hmma<<<grid, THREADS, SMEM_BYTES>>>(state, dstate, dval);
}

// round 10
// speedup vs baseline: 1.5841x; 1.0916x over previous
#include <cuda_runtime.h>
#include <cuda_fp16.h>
#include <cstdint>

// B=4, N=4096, D=256
// scores = (V V^T)/16 ; edges = softsign(scores)
// dstate = edges @ state ; dval = edges @ val
// fp16 pipeline: phase A 2-term (A_hi x (B_hi + B_lo)), phase B 1-term
// (E fp16 x V_hi). cp.async double-buffered, term-major mma scheduling.

#define BATCH 4
#define NN 4096
#define DD 256
#define BM 128
#define BJH 32            // half j-tile (pipeline stage)
#define NHALF (NN / BJH)  // 128
#define THREADS 256
#define ROWB 528          // 33 x 16B per 256-elem fp16 row (conflict-free padding)

static constexpr uint32_t S_VIH = 0;                     // Vi hi only: 128*528
static constexpr uint32_t S_VJ0 = 128u * ROWB;           //  67584
static constexpr uint32_t VJ_LO = 32u * ROWB;            //  16896 (lo offset in buffer)
static constexpr uint32_t VJBUF = 64u * ROWB;            //  33792
static constexpr uint32_t S_VJ1 = S_VJ0 + VJBUF;         // 101376
static constexpr uint32_t S_ST0 = S_VJ1 + VJBUF;         // 135168
static constexpr uint32_t S_ST1 = S_ST0 + 128u;
static constexpr uint32_t SMEM_BYTES = S_ST1 + 128u;     // 135424

__device__ __half g_vhi[(size_t)BATCH * NN * DD];
__device__ __half g_vlo[(size_t)BATCH * NN * DD];

__device__ __forceinline__ uint32_t smem_u32(const void* p) {
    uint32_t a;
    asm("{ .reg .u64 t; cvta.to.shared.u64 t, %1; cvt.u32.u64 %0, t; }" : "=r"(a) : "l"(p));
    return a;
}
__device__ __forceinline__ void cpa16(uint32_t dst, const void* src) {
    asm volatile("cp.async.cg.shared.global [%0], [%1], 16;" :: "r"(dst), "l"(src) : "memory");
}
#define CP_COMMIT() asm volatile("cp.async.commit_group;" ::: "memory")
#define CP_WAIT1()  asm volatile("cp.async.wait_group 1;" ::: "memory")

__device__ __forceinline__ void ldm_x4(uint32_t* r, uint32_t addr) {
    asm volatile("ldmatrix.sync.aligned.m8n8.x4.shared.b16 {%0,%1,%2,%3}, [%4];"
        : "=r"(r[0]), "=r"(r[1]), "=r"(r[2]), "=r"(r[3]) : "r"(addr));
}
__device__ __forceinline__ void ldm_x4_t(uint32_t* r, uint32_t addr) {
    asm volatile("ldmatrix.sync.aligned.m8n8.x4.trans.shared.b16 {%0,%1,%2,%3}, [%4];"
        : "=r"(r[0]), "=r"(r[1]), "=r"(r[2]), "=r"(r[3]) : "r"(addr));
}
__device__ __forceinline__ void mma16816(float* c, const uint32_t* a, const uint32_t* b) {
    asm volatile("mma.sync.aligned.m16n8k16.row.col.f32.f16.f16.f32 "
        "{%0,%1,%2,%3}, {%4,%5,%6,%7}, {%8,%9}, {%0,%1,%2,%3};"
        : "+f"(c[0]), "+f"(c[1]), "+f"(c[2]), "+f"(c[3])
        : "r"(a[0]), "r"(a[1]), "r"(a[2]), "r"(a[3]), "r"(b[0]), "r"(b[1]));
}
__device__ __forceinline__ uint32_t h2pk(float x, float y) {
    __half2 t = __floats2half2_rn(x, y);
    return *reinterpret_cast<uint32_t*>(&t);
}
__device__ __forceinline__ uint32_t h2lo(float x, float y) {
    float hx = __half2float(__float2half_rn(x));
    float hy = __half2float(__float2half_rn(y));
    __half2 t = __floats2half2_rn(x - hx, y - hy);
    return *reinterpret_cast<uint32_t*>(&t);
}

__global__ __launch_bounds__(256) void split_kernel(const float* __restrict__ val) {
    const int b = blockIdx.y, n0 = blockIdx.x * 64;
    const size_t base = ((size_t)b * NN + n0) * DD;
    #pragma unroll
    for (int k = 0; k < 16; k++) {
        int u = threadIdx.x + 256 * k;
        float4 v = *(const float4*)(val + base + (size_t)u * 4);
        *(uint2*)(g_vhi + base + (size_t)u * 4) = make_uint2(h2pk(v.x, v.y), h2pk(v.z, v.w));
        *(uint2*)(g_vlo + base + (size_t)u * 4) = make_uint2(h2lo(v.x, v.y), h2lo(v.z, v.w));
    }
}

__global__ __launch_bounds__(THREADS, 1)
void prop_hmma(const float* __restrict__ state,
               float* __restrict__ dstate, float* __restrict__ dval)
{
    extern __shared__ char smem[];
    const uint32_t sb = smem_u32(smem);
    const int tid = threadIdx.x, l = tid & 31, wid = tid >> 5;
    const int b = blockIdx.y, i0 = blockIdx.x * BM;
    const int mrow = wid * 16;
    const size_t vbase = (size_t)b * NN * DD;

    // ---- prologue fill: Vi (hi only) + j-half 0 ----
    {
        #pragma unroll
        for (int k = 0; k < 16; k++) {           // Vi hi: 4096 chunks
            int u = tid + 256 * k;
            int row = u >> 5, ch = u & 31;
            cpa16(sb + S_VIH + (uint32_t)(row * ROWB + ch * 16),
                  g_vhi + vbase + (size_t)(i0 + row) * DD + ch * 8);
        }
        #pragma unroll
        for (int k = 0; k < 8; k++) {            // Vj half 0: hi + lo
            int u = tid + 256 * k;
            int row = u >> 6, rem = u & 63;
            int half = rem >> 5, ch = rem & 31;
            cpa16(sb + S_VJ0 + (half ? VJ_LO : 0u) + (uint32_t)(row * ROWB + ch * 16),
                  (half ? g_vlo : g_vhi) + vbase + (size_t)row * DD + ch * 8);
        }
        if (tid < 8) cpa16(sb + S_ST0 + tid * 16, state + (size_t)b * NN + tid * 4);
        CP_COMMIT();
    }

    const uint32_t offA  = (uint32_t)((l & 15) * ROWB + (l >> 4) * 16);
    const uint32_t offBn = (uint32_t)(((l & 7) + ((l & 16) ? 8 : 0)) * ROWB + ((l >> 3) & 1) * 16);
    const uint32_t viH = sb + S_VIH + mrow * ROWB + offA;

    float dacc[32][4];
    #pragma unroll
    for (int t = 0; t < 32; t++) { dacc[t][0] = dacc[t][1] = dacc[t][2] = dacc[t][3] = 0.f; }
    float ds0 = 0.f, ds1 = 0.f;
    const float scale = 0.0625f;
    const int c0 = 2 * (l & 3);

    for (int h = 0; h < NHALF; h++) {
        // ---- issue fill(h+1) ----
        {
            int hn = h + 1;
            if (hn < NHALF) {
                const int j0 = hn * BJH;
                uint32_t bufb = sb + ((hn & 1) ? S_VJ1 : S_VJ0);
                #pragma unroll
                for (int k = 0; k < 8; k++) {
                    int u = tid + 256 * k;
                    int row = u >> 6, rem = u & 63;
                    int half = rem >> 5, ch = rem & 31;
                    cpa16(bufb + (half ? VJ_LO : 0u) + (uint32_t)(row * ROWB + ch * 16),
                          (half ? g_vlo : g_vhi) + vbase + (size_t)(j0 + row) * DD + ch * 8);
                }
                if (tid < 8)
                    cpa16(sb + ((hn & 1) ? S_ST1 : S_ST0) + tid * 16,
                          state + (size_t)b * NN + j0 + tid * 4);
            }
            CP_COMMIT();
        }
        CP_WAIT1();
        __syncthreads();

        const uint32_t bufb = sb + ((h & 1) ? S_VJ1 : S_VJ0);
        const uint32_t vjB = bufb + offBn;
        const uint32_t vjT = bufb + offA;
        const float* stp = (const float*)(smem + ((h & 1) ? S_ST1 : S_ST0));

        // ---- Phase A: 2-term fp16 (ah x bh + ah x bl), term-major ----
        float sacc[4][4];
        #pragma unroll
        for (int t = 0; t < 4; t++) { sacc[t][0] = sacc[t][1] = sacc[t][2] = sacc[t][3] = 0.f; }

        #pragma unroll
        for (int s = 0; s < 16; s++) {
            uint32_t ah[4], bh0[4], bh1[4], bl0[4], bl1[4];
            ldm_x4(ah, viH + s * 32);
            ldm_x4(bh0, vjB + s * 32);
            ldm_x4(bh1, vjB + 16 * ROWB + s * 32);
            ldm_x4(bl0, vjB + VJ_LO + s * 32);
            ldm_x4(bl1, vjB + VJ_LO + 16 * ROWB + s * 32);
            mma16816(sacc[0], ah, bh0 + 0);
            mma16816(sacc[1], ah, bh0 + 2);
            mma16816(sacc[2], ah, bh1 + 0);
            mma16816(sacc[3], ah, bh1 + 2);
            mma16816(sacc[0], ah, bl0 + 0);
            mma16816(sacc[1], ah, bl0 + 2);
            mma16816(sacc[2], ah, bl1 + 0);
            mma16816(sacc[3], ah, bl1 + 2);
        }

        // ---- epilogue: softsign (fp32), dstate partial, E -> fp16 a-frags ----
        uint32_t eh[2][4];
        #pragma unroll
        for (int t = 0; t < 4; t++) {
            float f0 = sacc[t][0] * scale, f1 = sacc[t][1] * scale;
            float f2 = sacc[t][2] * scale, f3 = sacc[t][3] * scale;
            float e0 = __fdividef(f0, 1.0f + fabsf(f0));
            float e1 = __fdividef(f1, 1.0f + fabsf(f1));
            float e2 = __fdividef(f2, 1.0f + fabsf(f2));
            float e3 = __fdividef(f3, 1.0f + fabsf(f3));
            float sA = stp[8 * t + c0], sB = stp[8 * t + c0 + 1];
            ds0 += e0 * sA + e1 * sB;
            ds1 += e2 * sA + e3 * sB;
            int kt = t >> 1, hh = (t & 1) * 2;
            eh[kt][hh]     = h2pk(e0, e1);
            eh[kt][hh + 1] = h2pk(e2, e3);
        }

        // ---- Phase B: 1-term (E fp16 x V_hi), blocks of 4, term-major ----
        #pragma unroll
        for (int kt = 0; kt < 2; kt++) {
            uint32_t tb = vjT + kt * (16 * ROWB);
            #pragma unroll
            for (int blk = 0; blk < 4; blk++) {
                uint32_t bh[4][4];
                #pragma unroll
                for (int j = 0; j < 4; j++)
                    ldm_x4_t(bh[j], tb + (blk * 4 + j) * 32);
                #pragma unroll
                for (int j = 0; j < 4; j++) {
                    int nt2 = blk * 4 + j;
                    mma16816(dacc[2 * nt2],     eh[kt], bh[j] + 0);
                    mma16816(dacc[2 * nt2 + 1], eh[kt], bh[j] + 2);
                }
            }
        }
        __syncthreads();
    }

    // ---- write dval ----
    {
        const int row = i0 + mrow + (l >> 2);
        float* d0 = dval + (size_t)b * NN * DD + (size_t)row * DD;
        float* d1 = d0 + 8 * DD;
        #pragma unroll
        for (int nt = 0; nt < 32; nt++) {
            int c = 8 * nt + c0;
            *(float2*)(d0 + c) = make_float2(dacc[nt][0], dacc[nt][1]);
            *(float2*)(d1 + c) = make_float2(dacc[nt][2], dacc[nt][3]);
        }
    }
    // ---- dstate ----
    ds0 += __shfl_xor_sync(0xFFFFFFFFu, ds0, 1);
    ds0 += __shfl_xor_sync(0xFFFFFFFFu, ds0, 2);
    ds1 += __shfl_xor_sync(0xFFFFFFFFu, ds1, 1);
    ds1 += __shfl_xor_sync(0xFFFFFFFFu, ds1, 2);
    if ((l & 3) == 0) {
        int r = i0 + mrow + (l >> 2);
        dstate[(size_t)b * NN + r]     = ds0;
        dstate[(size_t)b * NN + r + 8] = ds1;
    }
}

extern "C" void kernel_launch(void* const* d_in, const int* in_sizes, int n_in,
                              void* d_out, int out_size)
{
    const float* val   = (const float*)d_in[0];   // [B, N, D]
    const float* state = (const float*)d_in[1];   // [B, N]
    float* dstate = (float*)d_out;                // [B, N]
    float* dval   = dstate + (size_t)BATCH * NN;  // [B, N, D]
    (void)in_sizes; (void)n_in; (void)out_size;

    dim3 gs(NN / 64, BATCH);
    split_kernel<<<gs, 256>>>(val);

    cudaFuncSetAttribute(prop_hmma,
                         cudaFuncAttributeMaxDynamicSharedMemorySize, (int)SMEM_BYTES);
    dim3 grid(NN / BM, BATCH);
    prop_hmma<<<grid, THREADS, SMEM_BYTES>>>(state, dstate, dval);
}

// round 11
// speedup vs baseline: 1.6212x; 1.0235x over previous
#include <cuda_runtime.h>
#include <cuda_fp16.h>
#include <cstdint>

// B=4, N=4096, D=256
// scores = (V V^T)/16 ; edges = softsign(scores)
// dstate = edges @ state ; dval = edges @ val
// fp16 pipeline: phase A 2-term (A_hi x (B_hi + B_lo)), phase B 1-term
// (E fp16 x V_hi). cp.async double-buffered. BM=64 / 128 threads so TWO
// CTAs co-reside per SM: cross-CTA overlap covers mma/ldsm latency.

#define BATCH 4
#define NN 4096
#define DD 256
#define BM 64
#define BJH 32            // half j-tile (pipeline stage)
#define NHALF (NN / BJH)  // 128
#define THREADS 128
#define ROWB 528          // 33 x 16B per 256-elem fp16 row (conflict-free padding)

static constexpr uint32_t S_VIH = 0;                     // Vi hi: 64*528 = 33792
static constexpr uint32_t S_VJ0 = 64u * ROWB;            //  33792
static constexpr uint32_t VJ_LO = 32u * ROWB;            //  16896 (lo offset in buffer)
static constexpr uint32_t VJBUF = 64u * ROWB;            //  33792
static constexpr uint32_t S_VJ1 = S_VJ0 + VJBUF;         //  67584
static constexpr uint32_t S_ST0 = S_VJ1 + VJBUF;         // 101376
static constexpr uint32_t S_ST1 = S_ST0 + 128u;
static constexpr uint32_t SMEM_BYTES = S_ST1 + 128u;     // 101632  (x2 CTAs = 203264 < 228KB)

__device__ __half g_vhi[(size_t)BATCH * NN * DD];
__device__ __half g_vlo[(size_t)BATCH * NN * DD];

__device__ __forceinline__ uint32_t smem_u32(const void* p) {
    uint32_t a;
    asm("{ .reg .u64 t; cvta.to.shared.u64 t, %1; cvt.u32.u64 %0, t; }" : "=r"(a) : "l"(p));
    return a;
}
__device__ __forceinline__ void cpa16(uint32_t dst, const void* src) {
    asm volatile("cp.async.cg.shared.global [%0], [%1], 16;" :: "r"(dst), "l"(src) : "memory");
}
#define CP_COMMIT() asm volatile("cp.async.commit_group;" ::: "memory")
#define CP_WAIT1()  asm volatile("cp.async.wait_group 1;" ::: "memory")

__device__ __forceinline__ void ldm_x4(uint32_t* r, uint32_t addr) {
    asm volatile("ldmatrix.sync.aligned.m8n8.x4.shared.b16 {%0,%1,%2,%3}, [%4];"
        : "=r"(r[0]), "=r"(r[1]), "=r"(r[2]), "=r"(r[3]) : "r"(addr));
}
__device__ __forceinline__ void ldm_x4_t(uint32_t* r, uint32_t addr) {
    asm volatile("ldmatrix.sync.aligned.m8n8.x4.trans.shared.b16 {%0,%1,%2,%3}, [%4];"
        : "=r"(r[0]), "=r"(r[1]), "=r"(r[2]), "=r"(r[3]) : "r"(addr));
}
__device__ __forceinline__ void mma16816(float* c, const uint32_t* a, const uint32_t* b) {
    asm volatile("mma.sync.aligned.m16n8k16.row.col.f32.f16.f16.f32 "
        "{%0,%1,%2,%3}, {%4,%5,%6,%7}, {%8,%9}, {%0,%1,%2,%3};"
        : "+f"(c[0]), "+f"(c[1]), "+f"(c[2]), "+f"(c[3])
        : "r"(a[0]), "r"(a[1]), "r"(a[2]), "r"(a[3]), "r"(b[0]), "r"(b[1]));
}
__device__ __forceinline__ uint32_t h2pk(float x, float y) {
    __half2 t = __floats2half2_rn(x, y);
    return *reinterpret_cast<uint32_t*>(&t);
}
__device__ __forceinline__ uint32_t h2lo(float x, float y) {
    float hx = __half2float(__float2half_rn(x));
    float hy = __half2float(__float2half_rn(y));
    __half2 t = __floats2half2_rn(x - hx, y - hy);
    return *reinterpret_cast<uint32_t*>(&t);
}

__global__ __launch_bounds__(256) void split_kernel(const float* __restrict__ val) {
    const int b = blockIdx.y, n0 = blockIdx.x * 64;
    const size_t base = ((size_t)b * NN + n0) * DD;
    #pragma unroll
    for (int k = 0; k < 16; k++) {
        int u = threadIdx.x + 256 * k;
        float4 v = *(const float4*)(val + base + (size_t)u * 4);
        *(uint2*)(g_vhi + base + (size_t)u * 4) = make_uint2(h2pk(v.x, v.y), h2pk(v.z, v.w));
        *(uint2*)(g_vlo + base + (size_t)u * 4) = make_uint2(h2lo(v.x, v.y), h2lo(v.z, v.w));
    }
}

__global__ __launch_bounds__(THREADS, 2)
void prop_hmma(const float* __restrict__ state,
               float* __restrict__ dstate, float* __restrict__ dval)
{
    extern __shared__ char smem[];
    const uint32_t sb = smem_u32(smem);
    const int tid = threadIdx.x, l = tid & 31, wid = tid >> 5;
    const int b = blockIdx.y, i0 = blockIdx.x * BM;
    const int mrow = wid * 16;
    const size_t vbase = (size_t)b * NN * DD;

    // ---- prologue fill: Vi (hi only, 64 rows) + j-half 0 ----
    {
        #pragma unroll
        for (int k = 0; k < 16; k++) {           // Vi hi: 2048 chunks
            int u = tid + 128 * k;
            int row = u >> 5, ch = u & 31;
            cpa16(sb + S_VIH + (uint32_t)(row * ROWB + ch * 16),
                  g_vhi + vbase + (size_t)(i0 + row) * DD + ch * 8);
        }
        #pragma unroll
        for (int k = 0; k < 16; k++) {           // Vj half 0: hi + lo, 2048 chunks
            int u = tid + 128 * k;
            int row = u >> 6, rem = u & 63;
            int half = rem >> 5, ch = rem & 31;
            cpa16(sb + S_VJ0 + (half ? VJ_LO : 0u) + (uint32_t)(row * ROWB + ch * 16),
                  (half ? g_vlo : g_vhi) + vbase + (size_t)row * DD + ch * 8);
        }
        if (tid < 8) cpa16(sb + S_ST0 + tid * 16, state + (size_t)b * NN + tid * 4);
        CP_COMMIT();
    }

    const uint32_t offA  = (uint32_t)((l & 15) * ROWB + (l >> 4) * 16);
    const uint32_t offBn = (uint32_t)(((l & 7) + ((l & 16) ? 8 : 0)) * ROWB + ((l >> 3) & 1) * 16);
    const uint32_t viH = sb + S_VIH + mrow * ROWB + offA;

    float dacc[32][4];
    #pragma unroll
    for (int t = 0; t < 32; t++) { dacc[t][0] = dacc[t][1] = dacc[t][2] = dacc[t][3] = 0.f; }
    float ds0 = 0.f, ds1 = 0.f;
    const float scale = 0.0625f;
    const int c0 = 2 * (l & 3);

    for (int h = 0; h < NHALF; h++) {
        // ---- issue fill(h+1) ----
        {
            int hn = h + 1;
            if (hn < NHALF) {
                const int j0 = hn * BJH;
                uint32_t bufb = sb + ((hn & 1) ? S_VJ1 : S_VJ0);
                #pragma unroll
                for (int k = 0; k < 16; k++) {
                    int u = tid + 128 * k;
                    int row = u >> 6, rem = u & 63;
                    int half = rem >> 5, ch = rem & 31;
                    cpa16(bufb + (half ? VJ_LO : 0u) + (uint32_t)(row * ROWB + ch * 16),
                          (half ? g_vlo : g_vhi) + vbase + (size_t)(j0 + row) * DD + ch * 8);
                }
                if (tid < 8)
                    cpa16(sb + ((hn & 1) ? S_ST1 : S_ST0) + tid * 16,
                          state + (size_t)b * NN + j0 + tid * 4);
            }
            CP_COMMIT();
        }
        CP_WAIT1();
        __syncthreads();

        const uint32_t bufb = sb + ((h & 1) ? S_VJ1 : S_VJ0);
        const uint32_t vjB = bufb + offBn;
        const uint32_t vjT = bufb + offA;
        const float* stp = (const float*)(smem + ((h & 1) ? S_ST1 : S_ST0));

        // ---- Phase A: 2-term fp16 (ah x bh + ah x bl), term-major ----
        float sacc[4][4];
        #pragma unroll
        for (int t = 0; t < 4; t++) { sacc[t][0] = sacc[t][1] = sacc[t][2] = sacc[t][3] = 0.f; }

        #pragma unroll
        for (int s = 0; s < 16; s++) {
            uint32_t ah[4], bh0[4], bh1[4], bl0[4], bl1[4];
            ldm_x4(ah, viH + s * 32);
            ldm_x4(bh0, vjB + s * 32);
            ldm_x4(bh1, vjB + 16 * ROWB + s * 32);
            ldm_x4(bl0, vjB + VJ_LO + s * 32);
            ldm_x4(bl1, vjB + VJ_LO + 16 * ROWB + s * 32);
            mma16816(sacc[0], ah, bh0 + 0);
            mma16816(sacc[1], ah, bh0 + 2);
            mma16816(sacc[2], ah, bh1 + 0);
            mma16816(sacc[3], ah, bh1 + 2);
            mma16816(sacc[0], ah, bl0 + 0);
            mma16816(sacc[1], ah, bl0 + 2);
            mma16816(sacc[2], ah, bl1 + 0);
            mma16816(sacc[3], ah, bl1 + 2);
        }

        // ---- epilogue: softsign (fp32), dstate partial, E -> fp16 a-frags ----
        uint32_t eh[2][4];
        #pragma unroll
        for (int t = 0; t < 4; t++) {
            float f0 = sacc[t][0] * scale, f1 = sacc[t][1] * scale;
            float f2 = sacc[t][2] * scale, f3 = sacc[t][3] * scale;
            float e0 = __fdividef(f0, 1.0f + fabsf(f0));
            float e1 = __fdividef(f1, 1.0f + fabsf(f1));
            float e2 = __fdividef(f2, 1.0f + fabsf(f2));
            float e3 = __fdividef(f3, 1.0f + fabsf(f3));
            float sA = stp[8 * t + c0], sB = stp[8 * t + c0 + 1];
            ds0 += e0 * sA + e1 * sB;
            ds1 += e2 * sA + e3 * sB;
            int kt = t >> 1, hh = (t & 1) * 2;
            eh[kt][hh]     = h2pk(e0, e1);
            eh[kt][hh + 1] = h2pk(e2, e3);
        }

        // ---- Phase B: 1-term (E fp16 x V_hi), blocks of 4, term-major ----
        #pragma unroll
        for (int kt = 0; kt < 2; kt++) {
            uint32_t tb = vjT + kt * (16 * ROWB);
            #pragma unroll
            for (int blk = 0; blk < 4; blk++) {
                uint32_t bh[4][4];
                #pragma unroll
                for (int j = 0; j < 4; j++)
                    ldm_x4_t(bh[j], tb + (blk * 4 + j) * 32);
                #pragma unroll
                for (int j = 0; j < 4; j++) {
                    int nt2 = blk * 4 + j;
                    mma16816(dacc[2 * nt2],     eh[kt], bh[j] + 0);
                    mma16816(dacc[2 * nt2 + 1], eh[kt], bh[j] + 2);
                }
            }
        }
        __syncthreads();
    }

    // ---- write dval ----
    {
        const int row = i0 + mrow + (l >> 2);
        float* d0 = dval + (size_t)b * NN * DD + (size_t)row * DD;
        float* d1 = d0 + 8 * DD;
        #pragma unroll
        for (int nt = 0; nt < 32; nt++) {
            int c = 8 * nt + c0;
            *(float2*)(d0 + c) = make_float2(dacc[nt][0], dacc[nt][1]);
            *(float2*)(d1 + c) = make_float2(dacc[nt][2], dacc[nt][3]);
        }
    }
    // ---- dstate ----
    ds0 += __shfl_xor_sync(0xFFFFFFFFu, ds0, 1);
    ds0 += __shfl_xor_sync(0xFFFFFFFFu, ds0, 2);
    ds1 += __shfl_xor_sync(0xFFFFFFFFu, ds1, 1);
    ds1 += __shfl_xor_sync(0xFFFFFFFFu, ds1, 2);
    if ((l & 3) == 0) {
        int r = i0 + mrow + (l >> 2);
        dstate[(size_t)b * NN + r]     = ds0;
        dstate[(size_t)b * NN + r + 8] = ds1;
    }
}

extern "C" void kernel_launch(void* const* d_in, const int* in_sizes, int n_in,
                              void* d_out, int out_size)
{
    const float* val   = (const float*)d_in[0];   // [B, N, D]
    const float* state = (const float*)d_in[1];   // [B, N]
    float* dstate = (float*)d_out;                // [B, N]
    float* dval   = dstate + (size_t)BATCH * NN;  // [B, N, D]
    (void)in_sizes; (void)n_in; (void)out_size;

    dim3 gs(NN / 64, BATCH);
    split_kernel<<<gs, 256>>>(val);

    cudaFuncSetAttribute(prop_hmma,
                         cudaFuncAttributeMaxDynamicSharedMemorySize, (int)SMEM_BYTES);
    dim3 grid(NN / BM, BATCH);
    prop_hmma<<<grid, THREADS, SMEM_BYTES>>>(state, dstate, dval);
}

// round 12
// speedup vs baseline: 1.6379x; 1.0103x over previous
#include <cuda_runtime.h>
#include <cuda_fp16.h>
#include <cstdint>

// B=4, N=4096, D=256
// scores = (V V^T)/16 ; edges = softsign(scores)
// dstate = edges @ state ; dval = edges @ val
// fp16: phase A 2-term, 32x16 warp tiles (halved B duplication); E via smem;
// phase B 1-term 16x256. BM=64, 128 thr, 2 CTAs/SM, cp.async double-buffer.

#define BATCH 4
#define NN 4096
#define DD 256
#define BM 64
#define BJH 32
#define NHALF (NN / BJH)
#define THREADS 128
#define ROWB 528          // fp16 V-tile row pitch (conflict-free ldsm)
#define EP 80             // E row pitch (conflict-free STS + ldsm)

static constexpr uint32_t S_VIH = 0;                     // 64*528 = 33792
static constexpr uint32_t S_VJ0 = 33792;
static constexpr uint32_t VJ_LO = 16896;                 // 32*528
static constexpr uint32_t VJBUF = 33792;
static constexpr uint32_t S_VJ1 = S_VJ0 + VJBUF;         // 67584
static constexpr uint32_t S_E   = S_VJ1 + VJBUF;         // 101376: 64*80 = 5120
static constexpr uint32_t S_ST0 = 106496;
static constexpr uint32_t S_ST1 = 106624;
static constexpr uint32_t S_RED = 106752;                // 64*2*4 = 512
static constexpr uint32_t SMEM_BYTES = 107264;           // x2 CTAs = 214528 < 228KB

__device__ __half g_vhi[(size_t)BATCH * NN * DD];
__device__ __half g_vlo[(size_t)BATCH * NN * DD];

__device__ __forceinline__ uint32_t smem_u32(const void* p) {
    uint32_t a;
    asm("{ .reg .u64 t; cvta.to.shared.u64 t, %1; cvt.u32.u64 %0, t; }" : "=r"(a) : "l"(p));
    return a;
}
__device__ __forceinline__ void cpa16(uint32_t dst, const void* src) {
    asm volatile("cp.async.cg.shared.global [%0], [%1], 16;" :: "r"(dst), "l"(src) : "memory");
}
#define CP_COMMIT() asm volatile("cp.async.commit_group;" ::: "memory")
#define CP_WAIT1()  asm volatile("cp.async.wait_group 1;" ::: "memory")

__device__ __forceinline__ void ldm_x4(uint32_t* r, uint32_t addr) {
    asm volatile("ldmatrix.sync.aligned.m8n8.x4.shared.b16 {%0,%1,%2,%3}, [%4];"
        : "=r"(r[0]), "=r"(r[1]), "=r"(r[2]), "=r"(r[3]) : "r"(addr));
}
__device__ __forceinline__ void ldm_x4_t(uint32_t* r, uint32_t addr) {
    asm volatile("ldmatrix.sync.aligned.m8n8.x4.trans.shared.b16 {%0,%1,%2,%3}, [%4];"
        : "=r"(r[0]), "=r"(r[1]), "=r"(r[2]), "=r"(r[3]) : "r"(addr));
}
__device__ __forceinline__ void mma16816(float* c, const uint32_t* a, const uint32_t* b) {
    asm volatile("mma.sync.aligned.m16n8k16.row.col.f32.f16.f16.f32 "
        "{%0,%1,%2,%3}, {%4,%5,%6,%7}, {%8,%9}, {%0,%1,%2,%3};"
        : "+f"(c[0]), "+f"(c[1]), "+f"(c[2]), "+f"(c[3])
        : "r"(a[0]), "r"(a[1]), "r"(a[2]), "r"(a[3]), "r"(b[0]), "r"(b[1]));
}
__device__ __forceinline__ uint32_t h2pk(float x, float y) {
    __half2 t = __floats2half2_rn(x, y);
    return *reinterpret_cast<uint32_t*>(&t);
}
__device__ __forceinline__ uint32_t h2lo(float x, float y) {
    float hx = __half2float(__float2half_rn(x));
    float hy = __half2float(__float2half_rn(y));
    __half2 t = __floats2half2_rn(x - hx, y - hy);
    return *reinterpret_cast<uint32_t*>(&t);
}

__global__ __launch_bounds__(256) void split_kernel(const float* __restrict__ val) {
    const int b = blockIdx.y, n0 = blockIdx.x * 64;
    const size_t base = ((size_t)b * NN + n0) * DD;
    #pragma unroll
    for (int k = 0; k < 16; k++) {
        int u = threadIdx.x + 256 * k;
        float4 v = *(const float4*)(val + base + (size_t)u * 4);
        *(uint2*)(g_vhi + base + (size_t)u * 4) = make_uint2(h2pk(v.x, v.y), h2pk(v.z, v.w));
        *(uint2*)(g_vlo + base + (size_t)u * 4) = make_uint2(h2lo(v.x, v.y), h2lo(v.z, v.w));
    }
}

__global__ __launch_bounds__(THREADS, 2)
void prop_hmma(const float* __restrict__ state,
               float* __restrict__ dstate, float* __restrict__ dval)
{
    extern __shared__ char smem[];
    const uint32_t sb = smem_u32(smem);
    const int tid = threadIdx.x, l = tid & 31, wid = tid >> 5;
    const int arow0 = (wid >> 1) * 32, jh = wid & 1;      // phase A tile
    const int b = blockIdx.y, i0 = blockIdx.x * BM;
    const size_t vbase = (size_t)b * NN * DD;

    // ---- prologue fill: Vi (hi, 64 rows) + j-half 0 ----
    {
        #pragma unroll
        for (int k = 0; k < 16; k++) {
            int u = tid + 128 * k;
            int row = u >> 5, ch = u & 31;
            cpa16(sb + S_VIH + (uint32_t)(row * ROWB + ch * 16),
                  g_vhi + vbase + (size_t)(i0 + row) * DD + ch * 8);
        }
        #pragma unroll
        for (int k = 0; k < 16; k++) {
            int u = tid + 128 * k;
            int row = u >> 6, rem = u & 63;
            int half = rem >> 5, ch = rem & 31;
            cpa16(sb + S_VJ0 + (half ? VJ_LO : 0u) + (uint32_t)(row * ROWB + ch * 16),
                  (half ? g_vlo : g_vhi) + vbase + (size_t)row * DD + ch * 8);
        }
        if (tid < 8) cpa16(sb + S_ST0 + tid * 16, state + (size_t)b * NN + tid * 4);
        CP_COMMIT();
    }

    const uint32_t offA  = (uint32_t)((l & 15) * ROWB + (l >> 4) * 16);
    const uint32_t offAE = (uint32_t)((l & 15) * EP + (l >> 4) * 16);
    const uint32_t offBn = (uint32_t)(((l & 7) + ((l & 16) ? 8 : 0)) * ROWB + ((l >> 3) & 1) * 16);
    const uint32_t viH0 = sb + S_VIH + arow0 * ROWB + offA;       // +16*ROWB: mt=1
    const uint32_t eA   = sb + S_E + wid * (16 * EP) + offAE;     // phase B rows

    float dacc[32][4];
    #pragma unroll
    for (int t = 0; t < 32; t++) { dacc[t][0] = dacc[t][1] = dacc[t][2] = dacc[t][3] = 0.f; }
    float dsp[4] = {0.f, 0.f, 0.f, 0.f};
    const float scale = 0.0625f;
    const int c0 = 2 * (l & 3);

    for (int h = 0; h < NHALF; h++) {
        // ---- issue fill(h+1) ----
        {
            int hn = h + 1;
            if (hn < NHALF) {
                const int j0 = hn * BJH;
                uint32_t bufb = sb + ((hn & 1) ? S_VJ1 : S_VJ0);
                #pragma unroll
                for (int k = 0; k < 16; k++) {
                    int u = tid + 128 * k;
                    int row = u >> 6, rem = u & 63;
                    int half = rem >> 5, ch = rem & 31;
                    cpa16(bufb + (half ? VJ_LO : 0u) + (uint32_t)(row * ROWB + ch * 16),
                          (half ? g_vlo : g_vhi) + vbase + (size_t)(j0 + row) * DD + ch * 8);
                }
                if (tid < 8)
                    cpa16(sb + ((hn & 1) ? S_ST1 : S_ST0) + tid * 16,
                          state + (size_t)b * NN + j0 + tid * 4);
            }
            CP_COMMIT();
        }
        CP_WAIT1();
        __syncthreads();

        const uint32_t bufb = sb + ((h & 1) ? S_VJ1 : S_VJ0);
        const uint32_t vjB = bufb + (uint32_t)(jh * 16 * ROWB) + offBn;  // this j-half
        const uint32_t vjT = bufb + offA;
        const float* stp = (const float*)(smem + ((h & 1) ? S_ST1 : S_ST0));

        // ---- Phase A: S[32 x 16] per warp, 2-term, term-major ----
        float sacc[4][4];   // [mt*2 + nt]
        #pragma unroll
        for (int t = 0; t < 4; t++) { sacc[t][0] = sacc[t][1] = sacc[t][2] = sacc[t][3] = 0.f; }

        #pragma unroll
        for (int s = 0; s < 16; s++) {
            uint32_t ah0[4], ah1[4], bh[4], bl[4];
            ldm_x4(ah0, viH0 + s * 32);
            ldm_x4(ah1, viH0 + 16 * ROWB + s * 32);
            ldm_x4(bh, vjB + s * 32);
            ldm_x4(bl, vjB + VJ_LO + s * 32);
            mma16816(sacc[0], ah0, bh + 0);
            mma16816(sacc[1], ah0, bh + 2);
            mma16816(sacc[2], ah1, bh + 0);
            mma16816(sacc[3], ah1, bh + 2);
            mma16816(sacc[0], ah0, bl + 0);
            mma16816(sacc[1], ah0, bl + 2);
            mma16816(sacc[2], ah1, bl + 0);
            mma16816(sacc[3], ah1, bl + 2);
        }

        // ---- epilogue: softsign, dstate partials, E -> smem (fp16) ----
        #pragma unroll
        for (int mt = 0; mt < 2; mt++) {
            #pragma unroll
            for (int nt = 0; nt < 2; nt++) {
                const float* sc = sacc[mt * 2 + nt];
                float f0 = sc[0] * scale, f1 = sc[1] * scale;
                float f2 = sc[2] * scale, f3 = sc[3] * scale;
                float e0 = __fdividef(f0, 1.0f + fabsf(f0));
                float e1 = __fdividef(f1, 1.0f + fabsf(f1));
                float e2 = __fdividef(f2, 1.0f + fabsf(f2));
                float e3 = __fdividef(f3, 1.0f + fabsf(f3));
                int col = jh * 16 + nt * 8 + c0;
                float sA = stp[col], sB = stp[col + 1];
                dsp[mt * 2 + 0] += e0 * sA + e1 * sB;
                dsp[mt * 2 + 1] += e2 * sA + e3 * sB;
                uint32_t ea = sb + S_E + (uint32_t)((arow0 + mt * 16 + (l >> 2)) * EP + col * 2);
                asm volatile("st.shared.b32 [%0], %1;" :: "r"(ea), "r"(h2pk(e0, e1)));
                asm volatile("st.shared.b32 [%0], %1;" :: "r"(ea + 8 * EP), "r"(h2pk(e2, e3)));
            }
        }
        __syncthreads();   // E visible to all warps

        // ---- Phase B: dval[16 x 256] += E[16x32] @ Vj_hi[32x256] ----
        #pragma unroll
        for (int kt = 0; kt < 2; kt++) {
            uint32_t ehf[4];
            ldm_x4(ehf, eA + kt * 32);
            uint32_t tb = vjT + kt * (16 * ROWB);
            #pragma unroll
            for (int blk = 0; blk < 4; blk++) {
                uint32_t bhf[4][4];
                #pragma unroll
                for (int j = 0; j < 4; j++)
                    ldm_x4_t(bhf[j], tb + (blk * 4 + j) * 32);
                #pragma unroll
                for (int j = 0; j < 4; j++) {
                    int nt2 = blk * 4 + j;
                    mma16816(dacc[2 * nt2],     ehf, bhf[j] + 0);
                    mma16816(dacc[2 * nt2 + 1], ehf, bhf[j] + 2);
                }
            }
        }
        __syncthreads();   // all reads of buf/E done before next-iter overwrite
    }

    // ---- write dval (phase B ownership: rows wid*16..+16, all 256 cols) ----
    {
        const int row = i0 + wid * 16 + (l >> 2);
        float* d0 = dval + (size_t)b * NN * DD + (size_t)row * DD;
        float* d1 = d0 + 8 * DD;
        #pragma unroll
        for (int nt = 0; nt < 32; nt++) {
            int c = 8 * nt + c0;
            *(float2*)(d0 + c) = make_float2(dacc[nt][0], dacc[nt][1]);
            *(float2*)(d1 + c) = make_float2(dacc[nt][2], dacc[nt][3]);
        }
    }
    // ---- dstate: lane-reduce (4 lanes/row), then cross-jh reduce via smem ----
    #pragma unroll
    for (int t = 0; t < 4; t++) {
        dsp[t] += __shfl_xor_sync(0xFFFFFFFFu, dsp[t], 1);
        dsp[t] += __shfl_xor_sync(0xFFFFFFFFu, dsp[t], 2);
    }
    float* red = (float*)(smem + S_RED);
    if ((l & 3) == 0) {
        #pragma unroll
        for (int mt = 0; mt < 2; mt++) {
            int r = arow0 + mt * 16 + (l >> 2);
            red[r * 2 + jh]       = dsp[mt * 2];
            red[(r + 8) * 2 + jh] = dsp[mt * 2 + 1];
        }
    }
    __syncthreads();
    if (tid < BM)
        dstate[(size_t)b * NN + i0 + tid] = red[tid * 2] + red[tid * 2 + 1];
}

extern "C" void kernel_launch(void* const* d_in, const int* in_sizes, int n_in,
                              void* d_out, int out_size)
{
    const float* val   = (const float*)d_in[0];   // [B, N, D]
    const float* state = (const float*)d_in[1];   // [B, N]
    float* dstate = (float*)d_out;                // [B, N]
    float* dval   = dstate + (size_t)BATCH * NN;  // [B, N, D]
    (void)in_sizes; (void)n_in; (void)out_size;

    dim3 gs(NN / 64, BATCH);
    split_kernel<<<gs, 256>>>(val);

    cudaFuncSetAttribute(prop_hmma,
                         cudaFuncAttributeMaxDynamicSharedMemorySize, (int)SMEM_BYTES);
    dim3 grid(NN / BM, BATCH);
    prop_hmma<<<grid, THREADS, SMEM_BYTES>>>(state, dstate, dval);
}

// round 13
// speedup vs baseline: 1.6659x; 1.0171x over previous
#include <cuda_runtime.h>
#include <cuda_fp16.h>
#include <cstdint>

// B=4, N=4096, D=256
// scores = (V V^T)/16 ; edges = softsign(scores)
// dstate = edges @ state ; dval = edges @ val
// fp16: phase A 2-term 32x16 warp tiles; E via smem; phase B 1-term with
// N-split warp ownership (64 rows x 64-col slice -> no B-frag duplication).
// BM=64, 128 thr, 2 CTAs/SM, cp.async double-buffer.

#define BATCH 4
#define NN 4096
#define DD 256
#define BM 64
#define BJH 32
#define NHALF (NN / BJH)
#define THREADS 128
#define ROWB 528          // fp16 V-tile row pitch (conflict-free ldsm)
#define EP 80             // E row pitch (conflict-free STS + ldsm)

static constexpr uint32_t S_VIH = 0;                     // 64*528 = 33792
static constexpr uint32_t S_VJ0 = 33792;
static constexpr uint32_t VJ_LO = 16896;                 // 32*528
static constexpr uint32_t VJBUF = 33792;
static constexpr uint32_t S_VJ1 = S_VJ0 + VJBUF;         // 67584
static constexpr uint32_t S_E   = S_VJ1 + VJBUF;         // 101376: 64*80 = 5120
static constexpr uint32_t S_ST0 = 106496;
static constexpr uint32_t S_ST1 = 106624;
static constexpr uint32_t S_RED = 106752;                // 64*2*4 = 512
static constexpr uint32_t SMEM_BYTES = 107264;           // x2 CTAs = 214528 < 228KB

__device__ __half g_vhi[(size_t)BATCH * NN * DD];
__device__ __half g_vlo[(size_t)BATCH * NN * DD];

__device__ __forceinline__ uint32_t smem_u32(const void* p) {
    uint32_t a;
    asm("{ .reg .u64 t; cvta.to.shared.u64 t, %1; cvt.u32.u64 %0, t; }" : "=r"(a) : "l"(p));
    return a;
}
__device__ __forceinline__ void cpa16(uint32_t dst, const void* src) {
    asm volatile("cp.async.cg.shared.global [%0], [%1], 16;" :: "r"(dst), "l"(src) : "memory");
}
#define CP_COMMIT() asm volatile("cp.async.commit_group;" ::: "memory")
#define CP_WAIT1()  asm volatile("cp.async.wait_group 1;" ::: "memory")

__device__ __forceinline__ void ldm_x4(uint32_t* r, uint32_t addr) {
    asm volatile("ldmatrix.sync.aligned.m8n8.x4.shared.b16 {%0,%1,%2,%3}, [%4];"
        : "=r"(r[0]), "=r"(r[1]), "=r"(r[2]), "=r"(r[3]) : "r"(addr));
}
__device__ __forceinline__ void ldm_x4_t(uint32_t* r, uint32_t addr) {
    asm volatile("ldmatrix.sync.aligned.m8n8.x4.trans.shared.b16 {%0,%1,%2,%3}, [%4];"
        : "=r"(r[0]), "=r"(r[1]), "=r"(r[2]), "=r"(r[3]) : "r"(addr));
}
__device__ __forceinline__ void mma16816(float* c, const uint32_t* a, const uint32_t* b) {
    asm volatile("mma.sync.aligned.m16n8k16.row.col.f32.f16.f16.f32 "
        "{%0,%1,%2,%3}, {%4,%5,%6,%7}, {%8,%9}, {%0,%1,%2,%3};"
        : "+f"(c[0]), "+f"(c[1]), "+f"(c[2]), "+f"(c[3])
        : "r"(a[0]), "r"(a[1]), "r"(a[2]), "r"(a[3]), "r"(b[0]), "r"(b[1]));
}
__device__ __forceinline__ uint32_t h2pk(float x, float y) {
    __half2 t = __floats2half2_rn(x, y);
    return *reinterpret_cast<uint32_t*>(&t);
}
__device__ __forceinline__ uint32_t h2lo(float x, float y) {
    float hx = __half2float(__float2half_rn(x));
    float hy = __half2float(__float2half_rn(y));
    __half2 t = __floats2half2_rn(x - hx, y - hy);
    return *reinterpret_cast<uint32_t*>(&t);
}

__global__ __launch_bounds__(256) void split_kernel(const float* __restrict__ val) {
    const int b = blockIdx.y, n0 = blockIdx.x * 64;
    const size_t base = ((size_t)b * NN + n0) * DD;
    #pragma unroll
    for (int k = 0; k < 16; k++) {
        int u = threadIdx.x + 256 * k;
        float4 v = *(const float4*)(val + base + (size_t)u * 4);
        *(uint2*)(g_vhi + base + (size_t)u * 4) = make_uint2(h2pk(v.x, v.y), h2pk(v.z, v.w));
        *(uint2*)(g_vlo + base + (size_t)u * 4) = make_uint2(h2lo(v.x, v.y), h2lo(v.z, v.w));
    }
}

__global__ __launch_bounds__(THREADS, 2)
void prop_hmma(const float* __restrict__ state,
               float* __restrict__ dstate, float* __restrict__ dval)
{
    extern __shared__ char smem[];
    const uint32_t sb = smem_u32(smem);
    const int tid = threadIdx.x, l = tid & 31, wid = tid >> 5;
    const int arow0 = (wid >> 1) * 32, jh = wid & 1;      // phase A tile
    const int b = blockIdx.y, i0 = blockIdx.x * BM;
    const size_t vbase = (size_t)b * NN * DD;

    // ---- prologue fill: Vi (hi, 64 rows) + j-half 0 ----
    {
        #pragma unroll
        for (int k = 0; k < 16; k++) {
            int u = tid + 128 * k;
            int row = u >> 5, ch = u & 31;
            cpa16(sb + S_VIH + (uint32_t)(row * ROWB + ch * 16),
                  g_vhi + vbase + (size_t)(i0 + row) * DD + ch * 8);
        }
        #pragma unroll
        for (int k = 0; k < 16; k++) {
            int u = tid + 128 * k;
            int row = u >> 6, rem = u & 63;
            int half = rem >> 5, ch = rem & 31;
            cpa16(sb + S_VJ0 + (half ? VJ_LO : 0u) + (uint32_t)(row * ROWB + ch * 16),
                  (half ? g_vlo : g_vhi) + vbase + (size_t)row * DD + ch * 8);
        }
        if (tid < 8) cpa16(sb + S_ST0 + tid * 16, state + (size_t)b * NN + tid * 4);
        CP_COMMIT();
    }

    const uint32_t offA  = (uint32_t)((l & 15) * ROWB + (l >> 4) * 16);
    const uint32_t offAE = (uint32_t)((l & 15) * EP + (l >> 4) * 16);
    const uint32_t offBn = (uint32_t)(((l & 7) + ((l & 16) ? 8 : 0)) * ROWB + ((l >> 3) & 1) * 16);
    const uint32_t viH0 = sb + S_VIH + arow0 * ROWB + offA;   // +16*ROWB: mt=1
    const uint32_t eA   = sb + S_E + offAE;                   // + mt*16*EP + kt*32

    float dacc[4][8][4];   // [m-tile][n8-tile within 64-col slice][frag]
    #pragma unroll
    for (int mt = 0; mt < 4; mt++)
        #pragma unroll
        for (int n8 = 0; n8 < 8; n8++)
            dacc[mt][n8][0] = dacc[mt][n8][1] = dacc[mt][n8][2] = dacc[mt][n8][3] = 0.f;
    float dsp[4] = {0.f, 0.f, 0.f, 0.f};
    const float scale = 0.0625f;
    const int c0 = 2 * (l & 3);

    for (int h = 0; h < NHALF; h++) {
        // ---- issue fill(h+1) ----
        {
            int hn = h + 1;
            if (hn < NHALF) {
                const int j0 = hn * BJH;
                uint32_t bufb = sb + ((hn & 1) ? S_VJ1 : S_VJ0);
                #pragma unroll
                for (int k = 0; k < 16; k++) {
                    int u = tid + 128 * k;
                    int row = u >> 6, rem = u & 63;
                    int half = rem >> 5, ch = rem & 31;
                    cpa16(bufb + (half ? VJ_LO : 0u) + (uint32_t)(row * ROWB + ch * 16),
                          (half ? g_vlo : g_vhi) + vbase + (size_t)(j0 + row) * DD + ch * 8);
                }
                if (tid < 8)
                    cpa16(sb + ((hn & 1) ? S_ST1 : S_ST0) + tid * 16,
                          state + (size_t)b * NN + j0 + tid * 4);
            }
            CP_COMMIT();
        }
        CP_WAIT1();
        __syncthreads();

        const uint32_t bufb = sb + ((h & 1) ? S_VJ1 : S_VJ0);
        const uint32_t vjB = bufb + (uint32_t)(jh * 16 * ROWB) + offBn;  // phase A, this j-half
        const uint32_t vjT = bufb + offA + (uint32_t)(wid * 128);        // phase B, this col slice
        const float* stp = (const float*)(smem + ((h & 1) ? S_ST1 : S_ST0));

        // ---- Phase A: S[32 x 16] per warp, 2-term, term-major ----
        float sacc[4][4];   // [mt*2 + nt]
        #pragma unroll
        for (int t = 0; t < 4; t++) { sacc[t][0] = sacc[t][1] = sacc[t][2] = sacc[t][3] = 0.f; }

        #pragma unroll
        for (int s = 0; s < 16; s++) {
            uint32_t ah0[4], ah1[4], bh[4], bl[4];
            ldm_x4(ah0, viH0 + s * 32);
            ldm_x4(ah1, viH0 + 16 * ROWB + s * 32);
            ldm_x4(bh, vjB + s * 32);
            ldm_x4(bl, vjB + VJ_LO + s * 32);
            mma16816(sacc[0], ah0, bh + 0);
            mma16816(sacc[1], ah0, bh + 2);
            mma16816(sacc[2], ah1, bh + 0);
            mma16816(sacc[3], ah1, bh + 2);
            mma16816(sacc[0], ah0, bl + 0);
            mma16816(sacc[1], ah0, bl + 2);
            mma16816(sacc[2], ah1, bl + 0);
            mma16816(sacc[3], ah1, bl + 2);
        }

        // ---- epilogue: softsign, dstate partials, E -> smem (fp16) ----
        #pragma unroll
        for (int mt = 0; mt < 2; mt++) {
            #pragma unroll
            for (int nt = 0; nt < 2; nt++) {
                const float* sc = sacc[mt * 2 + nt];
                float f0 = sc[0] * scale, f1 = sc[1] * scale;
                float f2 = sc[2] * scale, f3 = sc[3] * scale;
                float e0 = __fdividef(f0, 1.0f + fabsf(f0));
                float e1 = __fdividef(f1, 1.0f + fabsf(f1));
                float e2 = __fdividef(f2, 1.0f + fabsf(f2));
                float e3 = __fdividef(f3, 1.0f + fabsf(f3));
                int col = jh * 16 + nt * 8 + c0;
                float sA = stp[col], sB = stp[col + 1];
                dsp[mt * 2 + 0] += e0 * sA + e1 * sB;
                dsp[mt * 2 + 1] += e2 * sA + e3 * sB;
                uint32_t ea = sb + S_E + (uint32_t)((arow0 + mt * 16 + (l >> 2)) * EP + col * 2);
                asm volatile("st.shared.b32 [%0], %1;" :: "r"(ea), "r"(h2pk(e0, e1)));
                asm volatile("st.shared.b32 [%0], %1;" :: "r"(ea + 8 * EP), "r"(h2pk(e2, e3)));
            }
        }
        __syncthreads();   // E visible to all warps

        // ---- Phase B: dval[64 x 64-col slice] += E[64x32] @ Vj_hi slice ----
        #pragma unroll
        for (int kt = 0; kt < 2; kt++) {
            uint32_t ehf[4][4];
            #pragma unroll
            for (int mt = 0; mt < 4; mt++)
                ldm_x4(ehf[mt], eA + (uint32_t)(mt * 16 * EP) + kt * 32);
            uint32_t tb = vjT + kt * (16 * ROWB);
            uint32_t bhf[4][4];
            #pragma unroll
            for (int j = 0; j < 4; j++)
                ldm_x4_t(bhf[j], tb + j * 32);
            #pragma unroll
            for (int j = 0; j < 4; j++) {
                #pragma unroll
                for (int mt = 0; mt < 4; mt++) {
                    mma16816(dacc[mt][2 * j],     ehf[mt], bhf[j] + 0);
                    mma16816(dacc[mt][2 * j + 1], ehf[mt], bhf[j] + 2);
                }
            }
        }
        __syncthreads();   // all reads of buf/E done before next-iter overwrite
    }

    // ---- write dval (warp owns all 64 rows x cols wid*64..+64) ----
    {
        float* dvb = dval + (size_t)b * NN * DD + (size_t)i0 * DD + wid * 64;
        #pragma unroll
        for (int mt = 0; mt < 4; mt++) {
            float* d0 = dvb + (size_t)(mt * 16 + (l >> 2)) * DD;
            float* d1 = d0 + 8 * DD;
            #pragma unroll
            for (int n8 = 0; n8 < 8; n8++) {
                int c = 8 * n8 + c0;
                *(float2*)(d0 + c) = make_float2(dacc[mt][n8][0], dacc[mt][n8][1]);
                *(float2*)(d1 + c) = make_float2(dacc[mt][n8][2], dacc[mt][n8][3]);
            }
        }
    }
    // ---- dstate: lane-reduce (4 lanes/row), then cross-jh reduce via smem ----
    #pragma unroll
    for (int t = 0; t < 4; t++) {
        dsp[t] += __shfl_xor_sync(0xFFFFFFFFu, dsp[t], 1);
        dsp[t] += __shfl_xor_sync(0xFFFFFFFFu, dsp[t], 2);
    }
    float* red = (float*)(smem + S_RED);
    if ((l & 3) == 0) {
        #pragma unroll
        for (int mt = 0; mt < 2; mt++) {
            int r = arow0 + mt * 16 + (l >> 2);
            red[r * 2 + jh]       = dsp[mt * 2];
            red[(r + 8) * 2 + jh] = dsp[mt * 2 + 1];
        }
    }
    __syncthreads();
    if (tid < BM)
        dstate[(size_t)b * NN + i0 + tid] = red[tid * 2] + red[tid * 2 + 1];
}

extern "C" void kernel_launch(void* const* d_in, const int* in_sizes, int n_in,
                              void* d_out, int out_size)
{
    const float* val   = (const float*)d_in[0];   // [B, N, D]
    const float* state = (const float*)d_in[1];   // [B, N]
    float* dstate = (float*)d_out;                // [B, N]
    float* dval   = dstate + (size_t)BATCH * NN;  // [B, N, D]
    (void)in_sizes; (void)n_in; (void)out_size;

    dim3 gs(NN / 64, BATCH);
    split_kernel<<<gs, 256>>>(val);

    cudaFuncSetAttribute(prop_hmma,
                         cudaFuncAttributeMaxDynamicSharedMemorySize, (int)SMEM_BYTES);
    dim3 grid(NN / BM, BATCH);
    prop_hmma<<<grid, THREADS, SMEM_BYTES>>>(state, dstate, dval);
}

// round 14
// speedup vs baseline: 1.7335x; 1.0406x over previous
#include <cuda_runtime.h>
#include <cuda_fp16.h>
#include <cstdint>

// B=4, N=4096, D=256
// scores = (V V^T)/16 ; edges = softsign(scores)
// dstate = edges @ state ; dval = edges @ val
// One-barrier pipelined fp16 kernel: pass h runs phase B(h-1) + phase A(h).
// Vj triple-buffered, E double-buffered. BM=128, 256 thr, 1 CTA/SM, grid 128.

#define BATCH 4
#define NN 4096
#define DD 256
#define BM 128
#define BJ 32
#define NIT (NN / BJ)     // 128
#define THREADS 256
#define ROWB 528          // fp16 V-tile row pitch (conflict-free ldsm)
#define EP 80             // E row pitch (conflict-free STS + ldsm)
#define VJS 33792u        // one Vj stage: 32 rows hi (16896) + 32 rows lo
#define VJ_LO 16896u

static constexpr uint32_t S_VI  = 0;                      // 128*528 = 67584
static constexpr uint32_t S_VJ  = 67584;                  // 3 stages = 101376
static constexpr uint32_t S_E   = 168960;                 // 2 x (128*80) = 20480
static constexpr uint32_t S_ST  = 189440;                 // 3 x 128B
static constexpr uint32_t S_RED = 189824;                 // 128*2*4 = 1024
static constexpr uint32_t SMEM_BYTES = 190848;

__device__ __half g_vhi[(size_t)BATCH * NN * DD];
__device__ __half g_vlo[(size_t)BATCH * NN * DD];

__device__ __forceinline__ uint32_t smem_u32(const void* p) {
    uint32_t a;
    asm("{ .reg .u64 t; cvta.to.shared.u64 t, %1; cvt.u32.u64 %0, t; }" : "=r"(a) : "l"(p));
    return a;
}
__device__ __forceinline__ void cpa16(uint32_t dst, const void* src) {
    asm volatile("cp.async.cg.shared.global [%0], [%1], 16;" :: "r"(dst), "l"(src) : "memory");
}
#define CP_COMMIT()   asm volatile("cp.async.commit_group;" ::: "memory")
#define CP_WAIT_ALL() asm volatile("cp.async.wait_group 0;" ::: "memory")

__device__ __forceinline__ void ldm_x4(uint32_t* r, uint32_t addr) {
    asm volatile("ldmatrix.sync.aligned.m8n8.x4.shared.b16 {%0,%1,%2,%3}, [%4];"
        : "=r"(r[0]), "=r"(r[1]), "=r"(r[2]), "=r"(r[3]) : "r"(addr));
}
__device__ __forceinline__ void ldm_x4_t(uint32_t* r, uint32_t addr) {
    asm volatile("ldmatrix.sync.aligned.m8n8.x4.trans.shared.b16 {%0,%1,%2,%3}, [%4];"
        : "=r"(r[0]), "=r"(r[1]), "=r"(r[2]), "=r"(r[3]) : "r"(addr));
}
__device__ __forceinline__ void mma16816(float* c, const uint32_t* a, const uint32_t* b) {
    asm volatile("mma.sync.aligned.m16n8k16.row.col.f32.f16.f16.f32 "
        "{%0,%1,%2,%3}, {%4,%5,%6,%7}, {%8,%9}, {%0,%1,%2,%3};"
        : "+f"(c[0]), "+f"(c[1]), "+f"(c[2]), "+f"(c[3])
        : "r"(a[0]), "r"(a[1]), "r"(a[2]), "r"(a[3]), "r"(b[0]), "r"(b[1]));
}
__device__ __forceinline__ uint32_t h2pk(float x, float y) {
    __half2 t = __floats2half2_rn(x, y);
    return *reinterpret_cast<uint32_t*>(&t);
}
__device__ __forceinline__ uint32_t h2lo(float x, float y) {
    float hx = __half2float(__float2half_rn(x));
    float hy = __half2float(__float2half_rn(y));
    __half2 t = __floats2half2_rn(x - hx, y - hy);
    return *reinterpret_cast<uint32_t*>(&t);
}

__global__ __launch_bounds__(256) void split_kernel(const float* __restrict__ val) {
    const int b = blockIdx.y, n0 = blockIdx.x * 64;
    const size_t base = ((size_t)b * NN + n0) * DD;
    #pragma unroll
    for (int k = 0; k < 16; k++) {
        int u = threadIdx.x + 256 * k;
        float4 v = *(const float4*)(val + base + (size_t)u * 4);
        *(uint2*)(g_vhi + base + (size_t)u * 4) = make_uint2(h2pk(v.x, v.y), h2pk(v.z, v.w));
        *(uint2*)(g_vlo + base + (size_t)u * 4) = make_uint2(h2lo(v.x, v.y), h2lo(v.z, v.w));
    }
}

__global__ __launch_bounds__(THREADS, 1)
void prop_hmma(const float* __restrict__ state,
               float* __restrict__ dstate, float* __restrict__ dval)
{
    extern __shared__ char smem[];
    const uint32_t sb = smem_u32(smem);
    const int tid = threadIdx.x, l = tid & 31, wid = tid >> 5;
    const int arow0 = (wid >> 1) * 32, jh = wid & 1;      // phase A: 32 rows x 16-j half
    const int b = blockIdx.y, i0 = blockIdx.x * BM;
    const size_t vbase = (size_t)b * NN * DD;
    const float* stateb = state + (size_t)b * NN;

    // ---- prologue: Vi fill + stage 0 ----
    {
        #pragma unroll
        for (int k = 0; k < 16; k++) {            // Vi hi: 4096 chunks
            int u = tid + 256 * k;
            int row = u >> 5, ch = u & 31;
            cpa16(sb + S_VI + (uint32_t)(row * ROWB + ch * 16),
                  g_vhi + vbase + (size_t)(i0 + row) * DD + ch * 8);
        }
        #pragma unroll
        for (int k = 0; k < 8; k++) {             // stage 0: 2048 chunks
            int u = tid + 256 * k;
            int row = u >> 6, rem = u & 63;
            int half = rem >> 5, ch = rem & 31;
            cpa16(sb + S_VJ + (half ? VJ_LO : 0u) + (uint32_t)(row * ROWB + ch * 16),
                  (half ? g_vlo : g_vhi) + vbase + (size_t)row * DD + ch * 8);
        }
        if (tid < 8) cpa16(sb + S_ST + tid * 16, stateb + tid * 4);
        CP_COMMIT();
    }

    const uint32_t offA  = (uint32_t)((l & 15) * ROWB + (l >> 4) * 16);
    const uint32_t offAE = (uint32_t)((l & 15) * EP + (l >> 4) * 16);
    const uint32_t offBn = (uint32_t)(((l & 7) + ((l & 16) ? 8 : 0)) * ROWB + ((l >> 3) & 1) * 16);
    const uint32_t viH0  = sb + S_VI + arow0 * ROWB + offA;   // +16*ROWB for mt=1

    float dacc[8][4][4];    // phase B: 128 rows x 32-col slice
    #pragma unroll
    for (int mt = 0; mt < 8; mt++)
        #pragma unroll
        for (int n8 = 0; n8 < 4; n8++)
            dacc[mt][n8][0] = dacc[mt][n8][1] = dacc[mt][n8][2] = dacc[mt][n8][3] = 0.f;
    float dsp[4] = {0.f, 0.f, 0.f, 0.f};
    const float scale = 0.0625f;
    const int c0 = 2 * (l & 3);

    int cur3 = 0;    // h % 3

    for (int h = 0; h <= NIT; h++) {
        CP_WAIT_ALL();
        __syncthreads();

        // ---- fill(h+1) (post-barrier: clobbers stage (h-2)%3, readers done) ----
        if (h + 1 < NIT) {
            const int nx3 = (cur3 == 2) ? 0 : cur3 + 1;
            const int j0 = (h + 1) * BJ;
            uint32_t bufn = sb + S_VJ + (uint32_t)nx3 * VJS;
            #pragma unroll
            for (int k = 0; k < 8; k++) {
                int u = tid + 256 * k;
                int row = u >> 6, rem = u & 63;
                int half = rem >> 5, ch = rem & 31;
                cpa16(bufn + (half ? VJ_LO : 0u) + (uint32_t)(row * ROWB + ch * 16),
                      (half ? g_vlo : g_vhi) + vbase + (size_t)(j0 + row) * DD + ch * 8);
            }
            if (tid < 8) cpa16(sb + S_ST + (uint32_t)nx3 * 128u + tid * 16, stateb + j0 + tid * 4);
        }
        CP_COMMIT();

        // ---- Phase B(h-1): dval[128 x 32-col slice] += E @ Vj_hi ----
        if (h >= 1) {
            const int p3 = (cur3 == 0) ? 2 : cur3 - 1;
            const uint32_t bufp = sb + S_VJ + (uint32_t)p3 * VJS;
            const uint32_t eAb  = sb + S_E + (uint32_t)((h - 1) & 1) * 10240u + offAE;
            const uint32_t vjTb = bufp + offA + (uint32_t)(wid * 64);   // col slice wid*32
            #pragma unroll
            for (int kt = 0; kt < 2; kt++) {
                uint32_t bh0[4], bh1[4];
                ldm_x4_t(bh0, vjTb + kt * (16 * ROWB));
                ldm_x4_t(bh1, vjTb + kt * (16 * ROWB) + 32);
                #pragma unroll
                for (int mt = 0; mt < 8; mt++) {
                    uint32_t ef[4];
                    ldm_x4(ef, eAb + (uint32_t)(mt * 16 * EP) + kt * 32);
                    mma16816(dacc[mt][0], ef, bh0 + 0);
                    mma16816(dacc[mt][1], ef, bh0 + 2);
                    mma16816(dacc[mt][2], ef, bh1 + 0);
                    mma16816(dacc[mt][3], ef, bh1 + 2);
                }
            }
        }

        // ---- Phase A(h): S[32 x 16] 2-term, softsign, E -> E[h%2] ----
        if (h < NIT) {
            const uint32_t bufb = sb + S_VJ + (uint32_t)cur3 * VJS;
            const uint32_t vjB  = bufb + (uint32_t)(jh * 16 * ROWB) + offBn;
            const float* stp = (const float*)(smem + S_ST + (uint32_t)cur3 * 128u);
            const uint32_t eW = sb + S_E + (uint32_t)(h & 1) * 10240u;

            float sacc[4][4];
            #pragma unroll
            for (int t = 0; t < 4; t++) { sacc[t][0] = sacc[t][1] = sacc[t][2] = sacc[t][3] = 0.f; }

            #pragma unroll
            for (int s = 0; s < 16; s++) {
                uint32_t ah0[4], ah1[4], bh[4], bl[4];
                ldm_x4(ah0, viH0 + s * 32);
                ldm_x4(ah1, viH0 + 16 * ROWB + s * 32);
                ldm_x4(bh, vjB + s * 32);
                ldm_x4(bl, vjB + VJ_LO + s * 32);
                mma16816(sacc[0], ah0, bh + 0);
                mma16816(sacc[1], ah0, bh + 2);
                mma16816(sacc[2], ah1, bh + 0);
                mma16816(sacc[3], ah1, bh + 2);
                mma16816(sacc[0], ah0, bl + 0);
                mma16816(sacc[1], ah0, bl + 2);
                mma16816(sacc[2], ah1, bl + 0);
                mma16816(sacc[3], ah1, bl + 2);
            }

            #pragma unroll
            for (int mt = 0; mt < 2; mt++) {
                #pragma unroll
                for (int nt = 0; nt < 2; nt++) {
                    const float* sc = sacc[mt * 2 + nt];
                    float f0 = sc[0] * scale, f1 = sc[1] * scale;
                    float f2 = sc[2] * scale, f3 = sc[3] * scale;
                    float e0 = __fdividef(f0, 1.0f + fabsf(f0));
                    float e1 = __fdividef(f1, 1.0f + fabsf(f1));
                    float e2 = __fdividef(f2, 1.0f + fabsf(f2));
                    float e3 = __fdividef(f3, 1.0f + fabsf(f3));
                    int col = jh * 16 + nt * 8 + c0;
                    float sA = stp[col], sB = stp[col + 1];
                    dsp[mt * 2 + 0] += e0 * sA + e1 * sB;
                    dsp[mt * 2 + 1] += e2 * sA + e3 * sB;
                    uint32_t ea = eW + (uint32_t)((arow0 + mt * 16 + (l >> 2)) * EP + col * 2);
                    asm volatile("st.shared.b32 [%0], %1;" :: "r"(ea), "r"(h2pk(e0, e1)));
                    asm volatile("st.shared.b32 [%0], %1;" :: "r"(ea + 8 * EP), "r"(h2pk(e2, e3)));
                }
            }
        }

        cur3 = (cur3 == 2) ? 0 : cur3 + 1;
    }

    // ---- write dval (warp owns all 128 rows x cols wid*32..+32) ----
    {
        float* dvb = dval + (size_t)b * NN * DD + (size_t)i0 * DD + wid * 32;
        #pragma unroll
        for (int mt = 0; mt < 8; mt++) {
            float* d0 = dvb + (size_t)(mt * 16 + (l >> 2)) * DD;
            float* d1 = d0 + 8 * DD;
            #pragma unroll
            for (int n8 = 0; n8 < 4; n8++) {
                int c = 8 * n8 + c0;
                *(float2*)(d0 + c) = make_float2(dacc[mt][n8][0], dacc[mt][n8][1]);
                *(float2*)(d1 + c) = make_float2(dacc[mt][n8][2], dacc[mt][n8][3]);
            }
        }
    }
    // ---- dstate: lane-reduce, then cross-jh reduce via smem ----
    #pragma unroll
    for (int t = 0; t < 4; t++) {
        dsp[t] += __shfl_xor_sync(0xFFFFFFFFu, dsp[t], 1);
        dsp[t] += __shfl_xor_sync(0xFFFFFFFFu, dsp[t], 2);
    }
    float* red = (float*)(smem + S_RED);
    if ((l & 3) == 0) {
        #pragma unroll
        for (int mt = 0; mt < 2; mt++) {
            int r = arow0 + mt * 16 + (l >> 2);
            red[r * 2 + jh]       = dsp[mt * 2];
            red[(r + 8) * 2 + jh] = dsp[mt * 2 + 1];
        }
    }
    __syncthreads();
    if (tid < BM)
        dstate[(size_t)b * NN + i0 + tid] = red[tid * 2] + red[tid * 2 + 1];
}

extern "C" void kernel_launch(void* const* d_in, const int* in_sizes, int n_in,
                              void* d_out, int out_size)
{
    const float* val   = (const float*)d_in[0];   // [B, N, D]
    const float* state = (const float*)d_in[1];   // [B, N]
    float* dstate = (float*)d_out;                // [B, N]
    float* dval   = dstate + (size_t)BATCH * NN;  // [B, N, D]
    (void)in_sizes; (void)n_in; (void)out_size;

    dim3 gs(NN / 64, BATCH);
    split_kernel<<<gs, 256>>>(val);

    cudaFuncSetAttribute(prop_hmma,
                         cudaFuncAttributeMaxDynamicSharedMemorySize, (int)SMEM_BYTES);
    dim3 grid(NN / BM, BATCH);
    prop_hmma<<<grid, THREADS, SMEM_BYTES>>>(state, dstate, dval);
}

// round 15
// speedup vs baseline: 2.3077x; 1.3312x over previous
#include <cuda_runtime.h>
#include <cuda_fp16.h>
#include <cstdint>

// B=4, N=4096, D=256
// scores = (V V^T)/16 ; edges = softsign(scores)
// dstate = edges @ state ; dval = edges @ val
// Pure-fp16 HMMA flash kernel (hi-only operands; fp32 accumulate & softsign).
// One-barrier pipeline: pass h = phase B(h-1) + phase A(h). Vj triple-buffered,
// E double-buffered. BM=128, 256 thr, grid 128 = one wave.

#define BATCH 4
#define NN 4096
#define DD 256
#define BM 128
#define BJ 32
#define NIT (NN / BJ)     // 128
#define THREADS 256
#define ROWB 528          // fp16 V-tile row pitch (conflict-free ldsm)
#define EP 80             // E row pitch (conflict-free STS + ldsm)
#define VJS 16896u        // one Vj stage: 32 rows fp16

static constexpr uint32_t S_VI  = 0;                      // 128*528 = 67584
static constexpr uint32_t S_VJ  = 67584;                  // 3 stages = 50688
static constexpr uint32_t S_E   = 118272;                 // 2 x (128*80) = 20480
static constexpr uint32_t S_ST  = 138752;                 // 3 x 128B
static constexpr uint32_t S_RED = 139136;                 // 128*2*4 = 1024
static constexpr uint32_t SMEM_BYTES = 140160;

__device__ __half g_vhi[(size_t)BATCH * NN * DD];

__device__ __forceinline__ uint32_t smem_u32(const void* p) {
    uint32_t a;
    asm("{ .reg .u64 t; cvta.to.shared.u64 t, %1; cvt.u32.u64 %0, t; }" : "=r"(a) : "l"(p));
    return a;
}
__device__ __forceinline__ void cpa16(uint32_t dst, const void* src) {
    asm volatile("cp.async.cg.shared.global [%0], [%1], 16;" :: "r"(dst), "l"(src) : "memory");
}
#define CP_COMMIT()   asm volatile("cp.async.commit_group;" ::: "memory")
#define CP_WAIT_ALL() asm volatile("cp.async.wait_group 0;" ::: "memory")

__device__ __forceinline__ void ldm_x4(uint32_t* r, uint32_t addr) {
    asm volatile("ldmatrix.sync.aligned.m8n8.x4.shared.b16 {%0,%1,%2,%3}, [%4];"
        : "=r"(r[0]), "=r"(r[1]), "=r"(r[2]), "=r"(r[3]) : "r"(addr));
}
__device__ __forceinline__ void ldm_x4_t(uint32_t* r, uint32_t addr) {
    asm volatile("ldmatrix.sync.aligned.m8n8.x4.trans.shared.b16 {%0,%1,%2,%3}, [%4];"
        : "=r"(r[0]), "=r"(r[1]), "=r"(r[2]), "=r"(r[3]) : "r"(addr));
}
__device__ __forceinline__ void mma16816(float* c, const uint32_t* a, const uint32_t* b) {
    asm volatile("mma.sync.aligned.m16n8k16.row.col.f32.f16.f16.f32 "
        "{%0,%1,%2,%3}, {%4,%5,%6,%7}, {%8,%9}, {%0,%1,%2,%3};"
        : "+f"(c[0]), "+f"(c[1]), "+f"(c[2]), "+f"(c[3])
        : "r"(a[0]), "r"(a[1]), "r"(a[2]), "r"(a[3]), "r"(b[0]), "r"(b[1]));
}
__device__ __forceinline__ uint32_t h2pk(float x, float y) {
    __half2 t = __floats2half2_rn(x, y);
    return *reinterpret_cast<uint32_t*>(&t);
}

__global__ __launch_bounds__(256) void split_kernel(const float* __restrict__ val) {
    const int b = blockIdx.y, n0 = blockIdx.x * 64;
    const size_t base = ((size_t)b * NN + n0) * DD;
    #pragma unroll
    for (int k = 0; k < 16; k++) {
        int u = threadIdx.x + 256 * k;
        float4 v = *(const float4*)(val + base + (size_t)u * 4);
        *(uint2*)(g_vhi + base + (size_t)u * 4) = make_uint2(h2pk(v.x, v.y), h2pk(v.z, v.w));
    }
}

__global__ __launch_bounds__(THREADS, 1)
void prop_hmma(const float* __restrict__ state,
               float* __restrict__ dstate, float* __restrict__ dval)
{
    extern __shared__ char smem[];
    const uint32_t sb = smem_u32(smem);
    const int tid = threadIdx.x, l = tid & 31, wid = tid >> 5;
    const int arow0 = (wid >> 1) * 32, jh = wid & 1;      // phase A: 32 rows x 16-j half
    const int b = blockIdx.y, i0 = blockIdx.x * BM;
    const size_t vbase = (size_t)b * NN * DD;
    const float* stateb = state + (size_t)b * NN;

    // ---- prologue: Vi fill + stage 0 ----
    {
        #pragma unroll
        for (int k = 0; k < 16; k++) {            // Vi: 4096 chunks
            int u = tid + 256 * k;
            int row = u >> 5, ch = u & 31;
            cpa16(sb + S_VI + (uint32_t)(row * ROWB + ch * 16),
                  g_vhi + vbase + (size_t)(i0 + row) * DD + ch * 8);
        }
        #pragma unroll
        for (int k = 0; k < 4; k++) {             // stage 0: 1024 chunks
            int u = tid + 256 * k;
            int row = u >> 5, ch = u & 31;
            cpa16(sb + S_VJ + (uint32_t)(row * ROWB + ch * 16),
                  g_vhi + vbase + (size_t)row * DD + ch * 8);
        }
        if (tid < 8) cpa16(sb + S_ST + tid * 16, stateb + tid * 4);
        CP_COMMIT();
    }

    const uint32_t offA  = (uint32_t)((l & 15) * ROWB + (l >> 4) * 16);
    const uint32_t offAE = (uint32_t)((l & 15) * EP + (l >> 4) * 16);
    const uint32_t offBn = (uint32_t)(((l & 7) + ((l & 16) ? 8 : 0)) * ROWB + ((l >> 3) & 1) * 16);
    const uint32_t viH0  = sb + S_VI + arow0 * ROWB + offA;   // +16*ROWB for mt=1

    float dacc[8][4][4];    // phase B: 128 rows x 32-col slice
    #pragma unroll
    for (int mt = 0; mt < 8; mt++)
        #pragma unroll
        for (int n8 = 0; n8 < 4; n8++)
            dacc[mt][n8][0] = dacc[mt][n8][1] = dacc[mt][n8][2] = dacc[mt][n8][3] = 0.f;
    float dsp[4] = {0.f, 0.f, 0.f, 0.f};
    const float scale = 0.0625f;
    const int c0 = 2 * (l & 3);

    int cur3 = 0;    // h % 3

    for (int h = 0; h <= NIT; h++) {
        CP_WAIT_ALL();
        __syncthreads();

        // ---- fill(h+1) (post-barrier: clobbers stage (h-2)%3, readers done) ----
        if (h + 1 < NIT) {
            const int nx3 = (cur3 == 2) ? 0 : cur3 + 1;
            const int j0 = (h + 1) * BJ;
            uint32_t bufn = sb + S_VJ + (uint32_t)nx3 * VJS;
            #pragma unroll
            for (int k = 0; k < 4; k++) {
                int u = tid + 256 * k;
                int row = u >> 5, ch = u & 31;
                cpa16(bufn + (uint32_t)(row * ROWB + ch * 16),
                      g_vhi + vbase + (size_t)(j0 + row) * DD + ch * 8);
            }
            if (tid < 8) cpa16(sb + S_ST + (uint32_t)nx3 * 128u + tid * 16, stateb + j0 + tid * 4);
        }
        CP_COMMIT();

        // ---- Phase B(h-1): dval[128 x 32-col slice] += E @ Vj ----
        if (h >= 1) {
            const int p3 = (cur3 == 0) ? 2 : cur3 - 1;
            const uint32_t bufp = sb + S_VJ + (uint32_t)p3 * VJS;
            const uint32_t eAb  = sb + S_E + (uint32_t)((h - 1) & 1) * 10240u + offAE;
            const uint32_t vjTb = bufp + offA + (uint32_t)(wid * 64);   // col slice wid*32
            #pragma unroll
            for (int kt = 0; kt < 2; kt++) {
                uint32_t bh0[4], bh1[4];
                ldm_x4_t(bh0, vjTb + kt * (16 * ROWB));
                ldm_x4_t(bh1, vjTb + kt * (16 * ROWB) + 32);
                #pragma unroll
                for (int mt = 0; mt < 8; mt++) {
                    uint32_t ef[4];
                    ldm_x4(ef, eAb + (uint32_t)(mt * 16 * EP) + kt * 32);
                    mma16816(dacc[mt][0], ef, bh0 + 0);
                    mma16816(dacc[mt][1], ef, bh0 + 2);
                    mma16816(dacc[mt][2], ef, bh1 + 0);
                    mma16816(dacc[mt][3], ef, bh1 + 2);
                }
            }
        }

        // ---- Phase A(h): S[32 x 16] fp16, softsign, E -> E[h%2] ----
        if (h < NIT) {
            const uint32_t bufb = sb + S_VJ + (uint32_t)cur3 * VJS;
            const uint32_t vjB  = bufb + (uint32_t)(jh * 16 * ROWB) + offBn;
            const float* stp = (const float*)(smem + S_ST + (uint32_t)cur3 * 128u);
            const uint32_t eW = sb + S_E + (uint32_t)(h & 1) * 10240u;

            float sacc[4][4];
            #pragma unroll
            for (int t = 0; t < 4; t++) { sacc[t][0] = sacc[t][1] = sacc[t][2] = sacc[t][3] = 0.f; }

            #pragma unroll
            for (int s = 0; s < 16; s++) {
                uint32_t ah0[4], ah1[4], bh[4];
                ldm_x4(ah0, viH0 + s * 32);
                ldm_x4(ah1, viH0 + 16 * ROWB + s * 32);
                ldm_x4(bh, vjB + s * 32);
                mma16816(sacc[0], ah0, bh + 0);
                mma16816(sacc[1], ah0, bh + 2);
                mma16816(sacc[2], ah1, bh + 0);
                mma16816(sacc[3], ah1, bh + 2);
            }

            #pragma unroll
            for (int mt = 0; mt < 2; mt++) {
                #pragma unroll
                for (int nt = 0; nt < 2; nt++) {
                    const float* sc = sacc[mt * 2 + nt];
                    float f0 = sc[0] * scale, f1 = sc[1] * scale;
                    float f2 = sc[2] * scale, f3 = sc[3] * scale;
                    float e0 = __fdividef(f0, 1.0f + fabsf(f0));
                    float e1 = __fdividef(f1, 1.0f + fabsf(f1));
                    float e2 = __fdividef(f2, 1.0f + fabsf(f2));
                    float e3 = __fdividef(f3, 1.0f + fabsf(f3));
                    int col = jh * 16 + nt * 8 + c0;
                    float sA = stp[col], sB = stp[col + 1];
                    dsp[mt * 2 + 0] += e0 * sA + e1 * sB;
                    dsp[mt * 2 + 1] += e2 * sA + e3 * sB;
                    uint32_t ea = eW + (uint32_t)((arow0 + mt * 16 + (l >> 2)) * EP + col * 2);
                    asm volatile("st.shared.b32 [%0], %1;" :: "r"(ea), "r"(h2pk(e0, e1)));
                    asm volatile("st.shared.b32 [%0], %1;" :: "r"(ea + 8 * EP), "r"(h2pk(e2, e3)));
                }
            }
        }

        cur3 = (cur3 == 2) ? 0 : cur3 + 1;
    }

    // ---- write dval (warp owns all 128 rows x cols wid*32..+32) ----
    {
        float* dvb = dval + (size_t)b * NN * DD + (size_t)i0 * DD + wid * 32;
        #pragma unroll
        for (int mt = 0; mt < 8; mt++) {
            float* d0 = dvb + (size_t)(mt * 16 + (l >> 2)) * DD;
            float* d1 = d0 + 8 * DD;
            #pragma unroll
            for (int n8 = 0; n8 < 4; n8++) {
                int c = 8 * n8 + c0;
                *(float2*)(d0 + c) = make_float2(dacc[mt][n8][0], dacc[mt][n8][1]);
                *(float2*)(d1 + c) = make_float2(dacc[mt][n8][2], dacc[mt][n8][3]);
            }
        }
    }
    // ---- dstate: lane-reduce, then cross-jh reduce via smem ----
    #pragma unroll
    for (int t = 0; t < 4; t++) {
        dsp[t] += __shfl_xor_sync(0xFFFFFFFFu, dsp[t], 1);
        dsp[t] += __shfl_xor_sync(0xFFFFFFFFu, dsp[t], 2);
    }
    float* red = (float*)(smem + S_RED);
    if ((l & 3) == 0) {
        #pragma unroll
        for (int mt = 0; mt < 2; mt++) {
            int r = arow0 + mt * 16 + (l >> 2);
            red[r * 2 + jh]       = dsp[mt * 2];
            red[(r + 8) * 2 + jh] = dsp[mt * 2 + 1];
        }
    }
    __syncthreads();
    if (tid < BM)
        dstate[(size_t)b * NN + i0 + tid] = red[tid * 2] + red[tid * 2 + 1];
}

extern "C" void kernel_launch(void* const* d_in, const int* in_sizes, int n_in,
                              void* d_out, int out_size)
{
    const float* val   = (const float*)d_in[0];   // [B, N, D]
    const float* state = (const float*)d_in[1];   // [B, N]
    float* dstate = (float*)d_out;                // [B, N]
    float* dval   = dstate + (size_t)BATCH * NN;  // [B, N, D]
    (void)in_sizes; (void)n_in; (void)out_size;

    dim3 gs(NN / 64, BATCH);
    split_kernel<<<gs, 256>>>(val);

    cudaFuncSetAttribute(prop_hmma,
                         cudaFuncAttributeMaxDynamicSharedMemorySize, (int)SMEM_BYTES);
    dim3 grid(NN / BM, BATCH);
    prop_hmma<<<grid, THREADS, SMEM_BYTES>>>(state, dstate, dval);
}

// round 16
// speedup vs baseline: 2.6673x; 1.1558x over previous
#include <cuda_runtime.h>
#include <cuda_fp16.h>
#include <cstdint>

// B=4, N=4096, D=256
// scores = (V V^T)/16 ; edges = softsign(scores)
// dstate = edges @ state ; dval = edges @ val
// Pure-fp16 HMMA flash kernel, persistent A-fragments (Vi loaded to registers
// once). One-barrier pipeline: pass h = phase B(h-1) + phase A(h).
// Vj triple-buffered, E double-buffered. BM=128, 256 thr, grid 128 = one wave.

#define BATCH 4
#define NN 4096
#define DD 256
#define BM 128
#define BJ 32
#define NIT (NN / BJ)     // 128
#define THREADS 256
#define ROWB 528          // fp16 V-tile row pitch (conflict-free ldsm)
#define EP 80             // E row pitch (conflict-free STS + ldsm)
#define VJS 16896u        // one Vj stage: 32 rows fp16

static constexpr uint32_t S_VI  = 0;                      // 128*528 = 67584
static constexpr uint32_t S_VJ  = 67584;                  // 3 stages = 50688
static constexpr uint32_t S_E   = 118272;                 // 2 x (128*80) = 20480
static constexpr uint32_t S_ST  = 138752;                 // 3 x 128B
static constexpr uint32_t SMEM_BYTES = 139264;

__device__ __half g_vhi[(size_t)BATCH * NN * DD];

__device__ __forceinline__ uint32_t smem_u32(const void* p) {
    uint32_t a;
    asm("{ .reg .u64 t; cvta.to.shared.u64 t, %1; cvt.u32.u64 %0, t; }" : "=r"(a) : "l"(p));
    return a;
}
__device__ __forceinline__ void cpa16(uint32_t dst, const void* src) {
    asm volatile("cp.async.cg.shared.global [%0], [%1], 16;" :: "r"(dst), "l"(src) : "memory");
}
#define CP_COMMIT()   asm volatile("cp.async.commit_group;" ::: "memory")
#define CP_WAIT_ALL() asm volatile("cp.async.wait_group 0;" ::: "memory")

__device__ __forceinline__ void ldm_x4(uint32_t* r, uint32_t addr) {
    asm volatile("ldmatrix.sync.aligned.m8n8.x4.shared.b16 {%0,%1,%2,%3}, [%4];"
        : "=r"(r[0]), "=r"(r[1]), "=r"(r[2]), "=r"(r[3]) : "r"(addr));
}
__device__ __forceinline__ void ldm_x4_t(uint32_t* r, uint32_t addr) {
    asm volatile("ldmatrix.sync.aligned.m8n8.x4.trans.shared.b16 {%0,%1,%2,%3}, [%4];"
        : "=r"(r[0]), "=r"(r[1]), "=r"(r[2]), "=r"(r[3]) : "r"(addr));
}
__device__ __forceinline__ void mma16816(float* c, const uint32_t* a, const uint32_t* b) {
    asm volatile("mma.sync.aligned.m16n8k16.row.col.f32.f16.f16.f32 "
        "{%0,%1,%2,%3}, {%4,%5,%6,%7}, {%8,%9}, {%0,%1,%2,%3};"
        : "+f"(c[0]), "+f"(c[1]), "+f"(c[2]), "+f"(c[3])
        : "r"(a[0]), "r"(a[1]), "r"(a[2]), "r"(a[3]), "r"(b[0]), "r"(b[1]));
}
__device__ __forceinline__ uint32_t h2pk(float x, float y) {
    __half2 t = __floats2half2_rn(x, y);
    return *reinterpret_cast<uint32_t*>(&t);
}

__global__ __launch_bounds__(256) void split_kernel(const float* __restrict__ val) {
    const int b = blockIdx.y, n0 = blockIdx.x * 64;
    const size_t base = ((size_t)b * NN + n0) * DD;
    #pragma unroll
    for (int k = 0; k < 16; k++) {
        int u = threadIdx.x + 256 * k;
        float4 v = *(const float4*)(val + base + (size_t)u * 4);
        *(uint2*)(g_vhi + base + (size_t)u * 4) = make_uint2(h2pk(v.x, v.y), h2pk(v.z, v.w));
    }
}

__global__ __launch_bounds__(THREADS, 1)
void prop_hmma(const float* __restrict__ state,
               float* __restrict__ dstate, float* __restrict__ dval)
{
    extern __shared__ char smem[];
    const uint32_t sb = smem_u32(smem);
    const int tid = threadIdx.x, l = tid & 31, wid = tid >> 5;
    const int b = blockIdx.y, i0 = blockIdx.x * BM;
    const size_t vbase = (size_t)b * NN * DD;
    const float* stateb = state + (size_t)b * NN;

    // ---- prologue: Vi fill + stage 0 ----
    {
        #pragma unroll
        for (int k = 0; k < 16; k++) {            // Vi: 4096 chunks
            int u = tid + 256 * k;
            int row = u >> 5, ch = u & 31;
            cpa16(sb + S_VI + (uint32_t)(row * ROWB + ch * 16),
                  g_vhi + vbase + (size_t)(i0 + row) * DD + ch * 8);
        }
        #pragma unroll
        for (int k = 0; k < 4; k++) {             // stage 0: 1024 chunks
            int u = tid + 256 * k;
            int row = u >> 5, ch = u & 31;
            cpa16(sb + S_VJ + (uint32_t)(row * ROWB + ch * 16),
                  g_vhi + vbase + (size_t)row * DD + ch * 8);
        }
        if (tid < 8) cpa16(sb + S_ST + tid * 16, stateb + tid * 4);
        CP_COMMIT();
    }

    const uint32_t offA  = (uint32_t)((l & 15) * ROWB + (l >> 4) * 16);
    const uint32_t offAE = (uint32_t)((l & 15) * EP + (l >> 4) * 16);
    const uint32_t offBn = (uint32_t)(((l & 7) + ((l & 16) ? 8 : 0)) * ROWB + ((l >> 3) & 1) * 16);

    // ---- wait prologue, hoist persistent A fragments (16 rows per warp) ----
    uint32_t ap[16][4];
    {
        CP_WAIT_ALL();
        __syncthreads();
        const uint32_t viA = sb + S_VI + (uint32_t)(wid * 16 * ROWB) + offA;
        #pragma unroll
        for (int s = 0; s < 16; s++) ldm_x4(ap[s], viA + s * 32);
    }

    float dacc[8][4][4];    // phase B: 128 rows x 32-col slice
    #pragma unroll
    for (int mt = 0; mt < 8; mt++)
        #pragma unroll
        for (int n8 = 0; n8 < 4; n8++)
            dacc[mt][n8][0] = dacc[mt][n8][1] = dacc[mt][n8][2] = dacc[mt][n8][3] = 0.f;
    float ds0 = 0.f, ds1 = 0.f;
    const float scale = 0.0625f;
    const int c0 = 2 * (l & 3);

    int cur3 = 0;    // h % 3

    for (int h = 0; h <= NIT; h++) {
        CP_WAIT_ALL();
        __syncthreads();

        // ---- fill(h+1) (post-barrier: clobbers stage (h-2)%3, readers done) ----
        if (h + 1 < NIT) {
            const int nx3 = (cur3 == 2) ? 0 : cur3 + 1;
            const int j0 = (h + 1) * BJ;
            uint32_t bufn = sb + S_VJ + (uint32_t)nx3 * VJS;
            #pragma unroll
            for (int k = 0; k < 4; k++) {
                int u = tid + 256 * k;
                int row = u >> 5, ch = u & 31;
                cpa16(bufn + (uint32_t)(row * ROWB + ch * 16),
                      g_vhi + vbase + (size_t)(j0 + row) * DD + ch * 8);
            }
            if (tid < 8) cpa16(sb + S_ST + (uint32_t)nx3 * 128u + tid * 16, stateb + j0 + tid * 4);
        }
        CP_COMMIT();

        // ---- Phase B(h-1): dval[128 x 32-col slice] += E @ Vj ----
        if (h >= 1) {
            const int p3 = (cur3 == 0) ? 2 : cur3 - 1;
            const uint32_t bufp = sb + S_VJ + (uint32_t)p3 * VJS;
            const uint32_t eAb  = sb + S_E + (uint32_t)((h - 1) & 1) * 10240u + offAE;
            const uint32_t vjTb = bufp + offA + (uint32_t)(wid * 64);   // col slice wid*32
            #pragma unroll
            for (int kt = 0; kt < 2; kt++) {
                uint32_t bh0[4], bh1[4];
                ldm_x4_t(bh0, vjTb + kt * (16 * ROWB));
                ldm_x4_t(bh1, vjTb + kt * (16 * ROWB) + 32);
                #pragma unroll
                for (int mt = 0; mt < 8; mt++) {
                    uint32_t ef[4];
                    ldm_x4(ef, eAb + (uint32_t)(mt * 16 * EP) + kt * 32);
                    mma16816(dacc[mt][0], ef, bh0 + 0);
                    mma16816(dacc[mt][1], ef, bh0 + 2);
                    mma16816(dacc[mt][2], ef, bh1 + 0);
                    mma16816(dacc[mt][3], ef, bh1 + 2);
                }
            }
        }

        // ---- Phase A(h): S[16 x 32] per warp (A persistent), softsign, E ----
        if (h < NIT) {
            const uint32_t bufb = sb + S_VJ + (uint32_t)cur3 * VJS;
            const uint32_t vjB0 = bufb + offBn;                 // j 0..15
            const uint32_t vjB1 = bufb + 16 * ROWB + offBn;     // j 16..31
            const float* stp = (const float*)(smem + S_ST + (uint32_t)cur3 * 128u);
            const uint32_t eW = sb + S_E + (uint32_t)(h & 1) * 10240u;

            float sacc[4][4];
            #pragma unroll
            for (int t = 0; t < 4; t++) { sacc[t][0] = sacc[t][1] = sacc[t][2] = sacc[t][3] = 0.f; }

            #pragma unroll
            for (int s = 0; s < 16; s++) {
                uint32_t bh[4], bh2[4];
                ldm_x4(bh,  vjB0 + s * 32);
                ldm_x4(bh2, vjB1 + s * 32);
                mma16816(sacc[0], ap[s], bh + 0);
                mma16816(sacc[1], ap[s], bh + 2);
                mma16816(sacc[2], ap[s], bh2 + 0);
                mma16816(sacc[3], ap[s], bh2 + 2);
            }

            #pragma unroll
            for (int nt = 0; nt < 4; nt++) {
                const float* sc = sacc[nt];
                float f0 = sc[0] * scale, f1 = sc[1] * scale;
                float f2 = sc[2] * scale, f3 = sc[3] * scale;
                float e0 = __fdividef(f0, 1.0f + fabsf(f0));
                float e1 = __fdividef(f1, 1.0f + fabsf(f1));
                float e2 = __fdividef(f2, 1.0f + fabsf(f2));
                float e3 = __fdividef(f3, 1.0f + fabsf(f3));
                int col = nt * 8 + c0;
                float sA = stp[col], sB = stp[col + 1];
                ds0 += e0 * sA + e1 * sB;
                ds1 += e2 * sA + e3 * sB;
                uint32_t ea = eW + (uint32_t)((wid * 16 + (l >> 2)) * EP + col * 2);
                asm volatile("st.shared.b32 [%0], %1;" :: "r"(ea), "r"(h2pk(e0, e1)));
                asm volatile("st.shared.b32 [%0], %1;" :: "r"(ea + 8 * EP), "r"(h2pk(e2, e3)));
            }
        }

        cur3 = (cur3 == 2) ? 0 : cur3 + 1;
    }

    // ---- write dval (warp owns all 128 rows x cols wid*32..+32) ----
    {
        float* dvb = dval + (size_t)b * NN * DD + (size_t)i0 * DD + wid * 32;
        #pragma unroll
        for (int mt = 0; mt < 8; mt++) {
            float* d0 = dvb + (size_t)(mt * 16 + (l >> 2)) * DD;
            float* d1 = d0 + 8 * DD;
            #pragma unroll
            for (int n8 = 0; n8 < 4; n8++) {
                int c = 8 * n8 + c0;
                *(float2*)(d0 + c) = make_float2(dacc[mt][n8][0], dacc[mt][n8][1]);
                *(float2*)(d1 + c) = make_float2(dacc[mt][n8][2], dacc[mt][n8][3]);
            }
        }
    }
    // ---- dstate: warp owns rows wid*16..+16 completely; lane-reduce only ----
    ds0 += __shfl_xor_sync(0xFFFFFFFFu, ds0, 1);
    ds0 += __shfl_xor_sync(0xFFFFFFFFu, ds0, 2);
    ds1 += __shfl_xor_sync(0xFFFFFFFFu, ds1, 1);
    ds1 += __shfl_xor_sync(0xFFFFFFFFu, ds1, 2);
    if ((l & 3) == 0) {
        int r = i0 + wid * 16 + (l >> 2);
        dstate[(size_t)b * NN + r]     = ds0;
        dstate[(size_t)b * NN + r + 8] = ds1;
    }
}

extern "C" void kernel_launch(void* const* d_in, const int* in_sizes, int n_in,
                              void* d_out, int out_size)
{
    const float* val   = (const float*)d_in[0];   // [B, N, D]
    const float* state = (const float*)d_in[1];   // [B, N]
    float* dstate = (float*)d_out;                // [B, N]
    float* dval   = dstate + (size_t)BATCH * NN;  // [B, N, D]
    (void)in_sizes; (void)n_in; (void)out_size;

    dim3 gs(NN / 64, BATCH);
    split_kernel<<<gs, 256>>>(val);

    cudaFuncSetAttribute(prop_hmma,
                         cudaFuncAttributeMaxDynamicSharedMemorySize, (int)SMEM_BYTES);
    dim3 grid(NN / BM, BATCH);
    prop_hmma<<<grid, THREADS, SMEM_BYTES>>>(state, dstate, dval);
}